// round 7
// baseline (speedup 1.0000x reference)
#include <cuda_runtime.h>
#include <cuda_bf16.h>

// ---------------------------------------------------------------------------
// GATv2 (2 layers) + BN + ELU + linear classifier.
// Shapes fixed by the problem: N=50000, E=800000, IN=128, H=8, C=32, NC=2.
// Strategy: CSR-sorted edges (built once per launch), warp-per-node fused
// attention+epilogue kernels (no atomics), 128x128 vectorized-LDS SGEMM.
// ---------------------------------------------------------------------------

#define NMAX 50000
#define EMAX 800000
#define H_ 8
#define C_ 32
#define HC_ 256       // H*C
#define ETOTMAX (EMAX + NMAX)
#define EPS_ 1e-5f
#define SLOPE_ 0.2f

// ------------------------- static device scratch ---------------------------
__device__ float g_xl[(size_t)NMAX * HC_];
__device__ float g_xr[(size_t)NMAX * HC_];
__device__ float g_h [(size_t)NMAX * HC_];
__device__ float g_elog[(size_t)ETOTMAX * H_];
__device__ int   g_src[EMAX];
__device__ int   g_dst[EMAX];
__device__ int   g_off[NMAX + 1];
__device__ int   g_cnt[NMAX];        // counts, then cursor
__device__ int   g_esrc[ETOTMAX];    // CSR: src node per edge slot
__device__ int   g_is64;

// ------------------------- edge index conversion ----------------------------
__global__ void k_detect(const int* __restrict__ ei, int E) {
    int ok64 = 1;
    int limit = (E > 64) ? 64 : E;
    for (int i = 0; i < limit; i++) {
        if (ei[2 * i + 1] != 0) { ok64 = 0; break; }
    }
    g_is64 = ok64;
}

__global__ void k_convert(const void* __restrict__ ei, int E) {
    int i = blockIdx.x * blockDim.x + threadIdx.x;
    int tot = 2 * E;
    if (i >= tot) return;
    int v;
    if (g_is64) v = (int)((const long long*)ei)[i];
    else        v = ((const int*)ei)[i];
    if (i < E) g_src[i] = v;
    else       g_dst[i - E] = v;
}

// ------------------------- CSR build ----------------------------------------
__global__ void k_hist(int E, int N) {
    int i = blockIdx.x * blockDim.x + threadIdx.x;
    if (i < E)          atomicAdd(&g_cnt[g_dst[i]], 1);
    else if (i < E + N) atomicAdd(&g_cnt[i - E], 1);   // self loop
}

// single block, 1024 threads: sequential chunked inclusive scan
__global__ void k_scan(int N) {
    __shared__ int buf[1024];
    __shared__ int carry_s;
    if (threadIdx.x == 0) carry_s = 0;
    __syncthreads();
    for (int base = 0; base < N; base += 1024) {
        int i = base + threadIdx.x;
        int v = (i < N) ? g_cnt[i] : 0;
        buf[threadIdx.x] = v;
        __syncthreads();
#pragma unroll
        for (int off = 1; off < 1024; off <<= 1) {
            int t = (threadIdx.x >= off) ? buf[threadIdx.x - off] : 0;
            __syncthreads();
            buf[threadIdx.x] += t;
            __syncthreads();
        }
        int incl = buf[threadIdx.x] + carry_s;
        if (i < N) {
            g_off[i + 1] = incl;
            g_cnt[i] = incl - v;   // cursor = exclusive prefix
        }
        __syncthreads();
        if (threadIdx.x == 1023) carry_s = incl;
        __syncthreads();
    }
    if (threadIdx.x == 0) g_off[0] = 0;
}

__global__ void k_scatter(int E, int N) {
    int i = blockIdx.x * blockDim.x + threadIdx.x;
    if (i < E) {
        int pos = atomicAdd(&g_cnt[g_dst[i]], 1);
        g_esrc[pos] = g_src[i];
    } else if (i < E + N) {
        int n = i - E;
        int pos = atomicAdd(&g_cnt[n], 1);
        g_esrc[pos] = n;
    }
}

// ------------------------- SGEMM: C[M,Nn] = A[M,K] @ B[K,Nn] ----------------
// 128x128 tile, 8x8 microtile, 256 threads, K-step 16, vectorized LDS.
__global__ void __launch_bounds__(256, 2)
sgemm128(const float* __restrict__ A, const float* __restrict__ B,
         float* __restrict__ Cc, int M, int K, int Nn) {
    __shared__ float As[16][132];
    __shared__ float Bs[16][128];
    int t  = threadIdx.x;
    int tx = t & 15, ty = t >> 4;
    int row0 = blockIdx.y * 128, col0 = blockIdx.x * 128;
    float acc[8][8] = {};
    for (int k0 = 0; k0 < K; k0 += 16) {
#pragma unroll
        for (int i = 0; i < 2; i++) {
            int idx = t * 2 + i;          // 0..511
            int m = idx >> 2, kq = idx & 3;
            int gr = row0 + m;
            float4 v = make_float4(0.f, 0.f, 0.f, 0.f);
            if (gr < M) v = *(const float4*)(A + (long long)gr * K + k0 + kq * 4);
            As[kq * 4 + 0][m] = v.x;
            As[kq * 4 + 1][m] = v.y;
            As[kq * 4 + 2][m] = v.z;
            As[kq * 4 + 3][m] = v.w;
        }
#pragma unroll
        for (int i = 0; i < 2; i++) {
            int idx = t * 2 + i;
            int kk = idx >> 5, n4 = idx & 31;
            *(float4*)&Bs[kk][n4 * 4] =
                *(const float4*)(B + (long long)(k0 + kk) * Nn + col0 + n4 * 4);
        }
        __syncthreads();
#pragma unroll
        for (int kk = 0; kk < 16; kk++) {
            float a[8], b[8];
            *(float4*)(a)     = *(float4*)&As[kk][ty * 8];
            *(float4*)(a + 4) = *(float4*)&As[kk][ty * 8 + 4];
            *(float4*)(b)     = *(float4*)&Bs[kk][tx * 8];
            *(float4*)(b + 4) = *(float4*)&Bs[kk][tx * 8 + 4];
#pragma unroll
            for (int i = 0; i < 8; i++)
#pragma unroll
                for (int j = 0; j < 8; j++) acc[i][j] += a[i] * b[j];
        }
        __syncthreads();
    }
#pragma unroll
    for (int i = 0; i < 8; i++) {
        int gr = row0 + ty * 8 + i;
        if (gr < M) {
            float* cp = Cc + (long long)gr * Nn + col0 + tx * 8;
            *(float4*)(cp)     = *(float4*)&acc[i][0];
            *(float4*)(cp + 4) = *(float4*)&acc[i][4];
        }
    }
}

// ------------------------- fused per-node attention --------------------------
// Warp per destination node. Two loops over incoming (CSR) edges:
//  1) logits (leakyrelu dot att), running max, store logits
//  2) exp, denom, weighted aggregate in registers
// Then the layer-specific epilogue. No atomics anywhere.
__device__ __forceinline__ void gat_core(int n, int lane, const float4* att4,
                                         float4& o0, float4& o1) {
    int beg = g_off[n], end = g_off[n + 1];
    int h0 = lane >> 3;
    const float4* xr4 = (const float4*)(g_xr + (long long)n * HC_);
    float4 r0 = xr4[lane], r1 = xr4[lane + 32];
    float4 a0 = att4[lane], a1 = att4[lane + 32];
    float mx0 = -3.4e38f, mx1 = -3.4e38f;
    for (int i = beg; i < end; i++) {
        int s = g_esrc[i];
        const float4* xl4 = (const float4*)(g_xl + (long long)s * HC_);
        float4 l0 = xl4[lane], l1 = xl4[lane + 32];
        float v, s0 = 0.f, s1 = 0.f;
        v = l0.x + r0.x; v = (v > 0.f) ? v : SLOPE_ * v; s0 += v * a0.x;
        v = l0.y + r0.y; v = (v > 0.f) ? v : SLOPE_ * v; s0 += v * a0.y;
        v = l0.z + r0.z; v = (v > 0.f) ? v : SLOPE_ * v; s0 += v * a0.z;
        v = l0.w + r0.w; v = (v > 0.f) ? v : SLOPE_ * v; s0 += v * a0.w;
        v = l1.x + r1.x; v = (v > 0.f) ? v : SLOPE_ * v; s1 += v * a1.x;
        v = l1.y + r1.y; v = (v > 0.f) ? v : SLOPE_ * v; s1 += v * a1.y;
        v = l1.z + r1.z; v = (v > 0.f) ? v : SLOPE_ * v; s1 += v * a1.z;
        v = l1.w + r1.w; v = (v > 0.f) ? v : SLOPE_ * v; s1 += v * a1.w;
#pragma unroll
        for (int off = 4; off; off >>= 1) {
            s0 += __shfl_xor_sync(0xffffffffu, s0, off);
            s1 += __shfl_xor_sync(0xffffffffu, s1, off);
        }
        mx0 = fmaxf(mx0, s0);
        mx1 = fmaxf(mx1, s1);
        if ((lane & 7) == 0) {
            g_elog[(long long)i * H_ + h0]     = s0;
            g_elog[(long long)i * H_ + h0 + 4] = s1;
        }
    }
    float den0 = 0.f, den1 = 0.f;
    float4 ac0 = make_float4(0.f, 0.f, 0.f, 0.f);
    float4 ac1 = make_float4(0.f, 0.f, 0.f, 0.f);
    for (int i = beg; i < end; i++) {
        int s = g_esrc[i];
        float lg0 = g_elog[(long long)i * H_ + h0];
        float lg1 = g_elog[(long long)i * H_ + h0 + 4];
        float ex0 = __expf(lg0 - mx0);
        float ex1 = __expf(lg1 - mx1);
        den0 += ex0; den1 += ex1;
        const float4* xl4 = (const float4*)(g_xl + (long long)s * HC_);
        float4 l0 = xl4[lane], l1 = xl4[lane + 32];
        ac0.x += ex0 * l0.x; ac0.y += ex0 * l0.y;
        ac0.z += ex0 * l0.z; ac0.w += ex0 * l0.w;
        ac1.x += ex1 * l1.x; ac1.y += ex1 * l1.y;
        ac1.z += ex1 * l1.z; ac1.w += ex1 * l1.w;
    }
    float i0 = 1.f / den0, i1 = 1.f / den1;
    o0 = make_float4(ac0.x * i0, ac0.y * i0, ac0.z * i0, ac0.w * i0);
    o1 = make_float4(ac1.x * i1, ac1.y * i1, ac1.z * i1, ac1.w * i1);
}

// layer 0: h = elu(bn(out + b0)), concat layout [N, 256]
__global__ void gat_layer0(const float* __restrict__ att,
                           const float* __restrict__ b0, const float* __restrict__ g0,
                           const float* __restrict__ be0, const float* __restrict__ m0,
                           const float* __restrict__ v0, int N) {
    int lane = threadIdx.x & 31;
    int n = (blockIdx.x * blockDim.x + threadIdx.x) >> 5;
    if (n >= N) return;
    float4 o0, o1;
    gat_core(n, lane, (const float4*)att, o0, o1);
    float4* ph = (float4*)(g_h + (long long)n * HC_);
    float out[8] = {o0.x, o0.y, o0.z, o0.w, o1.x, o1.y, o1.z, o1.w};
#pragma unroll
    for (int half = 0; half < 2; half++) {
        int q = lane + half * 32;
        float4 bb = ((const float4*)b0)[q];
        float4 gg = ((const float4*)g0)[q];
        float4 be = ((const float4*)be0)[q];
        float4 mm = ((const float4*)m0)[q];
        float4 vv = ((const float4*)v0)[q];
        float r[4];
        float xb[4] = {out[half*4+0] + bb.x, out[half*4+1] + bb.y,
                       out[half*4+2] + bb.z, out[half*4+3] + bb.w};
        float mu[4] = {mm.x, mm.y, mm.z, mm.w};
        float va[4] = {vv.x, vv.y, vv.z, vv.w};
        float ga[4] = {gg.x, gg.y, gg.z, gg.w};
        float ba[4] = {be.x, be.y, be.z, be.w};
#pragma unroll
        for (int j = 0; j < 4; j++) {
            float xv = (xb[j] - mu[j]) * rsqrtf(va[j] + EPS_) * ga[j] + ba[j];
            r[j] = (xv > 0.f) ? xv : (__expf(xv) - 1.f);
        }
        ph[q] = make_float4(r[0], r[1], r[2], r[3]);
    }
}

// layer 1: s = bn(mean_h(out) + b1); y = s @ Wc + bc  -> out [N, 2]
__global__ void gat_layer1(const float* __restrict__ att,
                           const float* __restrict__ b1, const float* __restrict__ g1,
                           const float* __restrict__ be1, const float* __restrict__ m1,
                           const float* __restrict__ v1, const float* __restrict__ Wc,
                           const float* __restrict__ bc, float* __restrict__ outp, int N) {
    int lane = threadIdx.x & 31;
    int n = (blockIdx.x * blockDim.x + threadIdx.x) >> 5;
    if (n >= N) return;
    float4 o0, o1;
    gat_core(n, lane, (const float4*)att, o0, o1);
    // sum over 8 heads: o0 covers head lane>>3, o1 head (lane>>3)+4, channels (lane&7)*4..+3
    float t0 = o0.x + o1.x, t1 = o0.y + o1.y, t2 = o0.z + o1.z, t3 = o0.w + o1.w;
#pragma unroll
    for (int off = 8; off <= 16; off <<= 1) {
        t0 += __shfl_xor_sync(0xffffffffu, t0, off);
        t1 += __shfl_xor_sync(0xffffffffu, t1, off);
        t2 += __shfl_xor_sync(0xffffffffu, t2, off);
        t3 += __shfl_xor_sync(0xffffffffu, t3, off);
    }
    int cg = lane & 7;      // channel group: channels cg*4..cg*4+3
    float4 bb = ((const float4*)b1)[cg];
    float4 gg = ((const float4*)g1)[cg];
    float4 be = ((const float4*)be1)[cg];
    float4 mm = ((const float4*)m1)[cg];
    float4 vv = ((const float4*)v1)[cg];
    float s0 = (t0 * 0.125f + bb.x - mm.x) * rsqrtf(vv.x + EPS_) * gg.x + be.x;
    float s1 = (t1 * 0.125f + bb.y - mm.y) * rsqrtf(vv.y + EPS_) * gg.y + be.y;
    float s2 = (t2 * 0.125f + bb.z - mm.z) * rsqrtf(vv.z + EPS_) * gg.z + be.z;
    float s3 = (t3 * 0.125f + bb.w - mm.w) * rsqrtf(vv.w + EPS_) * gg.w + be.w;
    int c0 = cg * 4;
    float y0 = s0 * Wc[(c0+0)*2] + s1 * Wc[(c0+1)*2] + s2 * Wc[(c0+2)*2] + s3 * Wc[(c0+3)*2];
    float y1 = s0 * Wc[(c0+0)*2+1] + s1 * Wc[(c0+1)*2+1] + s2 * Wc[(c0+2)*2+1] + s3 * Wc[(c0+3)*2+1];
#pragma unroll
    for (int off = 4; off; off >>= 1) {
        y0 += __shfl_xor_sync(0xffffffffu, y0, off);
        y1 += __shfl_xor_sync(0xffffffffu, y1, off);
    }
    if (lane == 0) {
        outp[(long long)n * 2 + 0] = y0 + bc[0];
        outp[(long long)n * 2 + 1] = y1 + bc[1];
    }
}

// ---------------------------------------------------------------------------
extern "C" void kernel_launch(void* const* d_in, const int* in_sizes, int n_in,
                              void* d_out, int out_size) {
    const float* x    = (const float*)d_in[0];
    const void*  ei   = d_in[1];
    const float* Wl0  = (const float*)d_in[2];
    const float* Wr0  = (const float*)d_in[3];
    const float* att0 = (const float*)d_in[4];
    const float* b0   = (const float*)d_in[5];
    const float* g0   = (const float*)d_in[6];
    const float* be0  = (const float*)d_in[7];
    const float* m0   = (const float*)d_in[8];
    const float* v0   = (const float*)d_in[9];
    const float* Wl1  = (const float*)d_in[10];
    const float* Wr1  = (const float*)d_in[11];
    const float* att1 = (const float*)d_in[12];
    const float* b1   = (const float*)d_in[13];
    const float* g1   = (const float*)d_in[14];
    const float* be1  = (const float*)d_in[15];
    const float* m1   = (const float*)d_in[16];
    const float* v1   = (const float*)d_in[17];
    const float* Wc   = (const float*)d_in[18];
    const float* bc   = (const float*)d_in[19];
    float* out = (float*)d_out;

    int IN = in_sizes[2] / HC_;       // 128
    int N  = in_sizes[0] / IN;        // 50000
    int E  = in_sizes[1] / 2;         // 800000
    int Etot = E + N;

    void *p_xl, *p_xr, *p_h, *p_cnt;
    cudaGetSymbolAddress(&p_xl,  g_xl);
    cudaGetSymbolAddress(&p_xr,  g_xr);
    cudaGetSymbolAddress(&p_h,   g_h);
    cudaGetSymbolAddress(&p_cnt, g_cnt);

    // ---- edge index conversion + CSR build (once; reused by both layers) ----
    k_detect<<<1, 1>>>((const int*)ei, E);
    k_convert<<<(2 * E + 255) / 256, 256>>>(ei, E);
    cudaMemsetAsync(p_cnt, 0, (size_t)N * sizeof(int), 0);
    k_hist<<<(Etot + 255) / 256, 256>>>(E, N);
    k_scan<<<1, 1024>>>(N);
    k_scatter<<<(Etot + 255) / 256, 256>>>(E, N);

    dim3 ggrid(HC_ / 128, (N + 127) / 128);
    int nodeBlocks = (N * 32 + 255) / 256;

    // ---------------- layer 0 ----------------
    sgemm128<<<ggrid, 256>>>(x, Wl0, (float*)p_xl, N, IN, HC_);
    sgemm128<<<ggrid, 256>>>(x, Wr0, (float*)p_xr, N, IN, HC_);
    gat_layer0<<<nodeBlocks, 256>>>(att0, b0, g0, be0, m0, v0, N);

    // ---------------- layer 1 ----------------
    sgemm128<<<ggrid, 256>>>((const float*)p_h, Wl1, (float*)p_xl, N, HC_, HC_);
    sgemm128<<<ggrid, 256>>>((const float*)p_h, Wr1, (float*)p_xr, N, HC_, HC_);
    gat_layer1<<<nodeBlocks, 256>>>(att1, b1, g1, be1, m1, v1, Wc, bc, out, N);
}

// round 8
// speedup vs baseline: 1.6660x; 1.6660x over previous
#include <cuda_runtime.h>
#include <cuda_bf16.h>

// ---------------------------------------------------------------------------
// GATv2 (2 layers) + BN + ELU + linear classifier.
// N=50000, E=800000, IN=128, H=8, C=32, NC=2.
// CSR build (overlapped with layer-0 GEMMs), warp-per-node ONLINE-softmax
// fused attention+epilogue (single xl pass, no atomics), 128x128 SGEMM with
// paired-B launches (gridDim.z selects Wl/Wr).
// ---------------------------------------------------------------------------

#define NMAX 50000
#define EMAX 800000
#define H_ 8
#define C_ 32
#define HC_ 256       // H*C
#define ETOTMAX (EMAX + NMAX)
#define EPS_ 1e-5f
#define SLOPE_ 0.2f

// ------------------------- static device scratch ---------------------------
__device__ float g_xl[(size_t)NMAX * HC_];
__device__ float g_xr[(size_t)NMAX * HC_];
__device__ float g_h [(size_t)NMAX * HC_];
__device__ int   g_src[EMAX];
__device__ int   g_dst[EMAX];
__device__ int   g_off[NMAX + 1];
__device__ int   g_cnt[NMAX];        // counts, then cursor
__device__ int   g_esrc[ETOTMAX];    // CSR: src node per edge slot
__device__ int   g_is64;

// ------------------------- edge index conversion ----------------------------
__global__ void k_detect(const int* __restrict__ ei, int E) {
    int ok64 = 1;
    int limit = (E > 64) ? 64 : E;
    for (int i = 0; i < limit; i++) {
        if (ei[2 * i + 1] != 0) { ok64 = 0; break; }
    }
    g_is64 = ok64;
}

__global__ void k_convert(const void* __restrict__ ei, int E) {
    int i = blockIdx.x * blockDim.x + threadIdx.x;
    int tot = 2 * E;
    if (i >= tot) return;
    int v;
    if (g_is64) v = (int)((const long long*)ei)[i];
    else        v = ((const int*)ei)[i];
    if (i < E) g_src[i] = v;
    else       g_dst[i - E] = v;
}

// ------------------------- CSR build ----------------------------------------
__global__ void k_hist(int E, int N) {
    int i = blockIdx.x * blockDim.x + threadIdx.x;
    if (i < E)          atomicAdd(&g_cnt[g_dst[i]], 1);
    else if (i < E + N) atomicAdd(&g_cnt[i - E], 1);   // self loop
}

// single block, 1024 threads: per-thread sequential chunk + one block scan
__global__ void k_scan(int N) {
    __shared__ int sh[1024];
    int t = threadIdx.x;
    int chunk = (N + 1023) >> 10;
    int beg = t * chunk;
    int end = beg + chunk; if (end > N) end = N;
    int sum = 0;
    for (int i = beg; i < end; i++) sum += g_cnt[i];
    sh[t] = sum;
    __syncthreads();
#pragma unroll
    for (int off = 1; off < 1024; off <<= 1) {
        int v = (t >= off) ? sh[t - off] : 0;
        __syncthreads();
        sh[t] += v;
        __syncthreads();
    }
    int run = sh[t] - sum;          // exclusive prefix of this chunk
    for (int i = beg; i < end; i++) {
        int c = g_cnt[i];
        g_cnt[i] = run;             // cursor = exclusive prefix
        run += c;
        g_off[i + 1] = run;         // inclusive prefix
    }
    if (t == 0) g_off[0] = 0;
}

__global__ void k_scatter(int E, int N) {
    int i = blockIdx.x * blockDim.x + threadIdx.x;
    if (i < E) {
        int pos = atomicAdd(&g_cnt[g_dst[i]], 1);
        g_esrc[pos] = g_src[i];
    } else if (i < E + N) {
        int n = i - E;
        int pos = atomicAdd(&g_cnt[n], 1);
        g_esrc[pos] = n;
    }
}

// ------------------------- SGEMM pair: C[z] = A @ B[z] ----------------------
// 128x128 tile, 8x8 microtile, 256 threads, K-step 16. gridDim.z = 2 picks
// (B0->C0) or (B1->C1), so one launch does both the Wl and Wr projections.
__global__ void __launch_bounds__(256, 2)
sgemm128x2(const float* __restrict__ A,
           const float* __restrict__ B0, const float* __restrict__ B1,
           float* __restrict__ C0, float* __restrict__ C1,
           int M, int K, int Nn) {
    const float* B = (blockIdx.z == 0) ? B0 : B1;
    float*       Cc = (blockIdx.z == 0) ? C0 : C1;
    __shared__ float As[16][132];
    __shared__ float Bs[16][128];
    int t  = threadIdx.x;
    int tx = t & 15, ty = t >> 4;
    int row0 = blockIdx.y * 128, col0 = blockIdx.x * 128;
    float acc[8][8] = {};
    for (int k0 = 0; k0 < K; k0 += 16) {
#pragma unroll
        for (int i = 0; i < 2; i++) {
            int idx = t * 2 + i;          // 0..511
            int m = idx >> 2, kq = idx & 3;
            int gr = row0 + m;
            float4 v = make_float4(0.f, 0.f, 0.f, 0.f);
            if (gr < M) v = *(const float4*)(A + (long long)gr * K + k0 + kq * 4);
            As[kq * 4 + 0][m] = v.x;
            As[kq * 4 + 1][m] = v.y;
            As[kq * 4 + 2][m] = v.z;
            As[kq * 4 + 3][m] = v.w;
        }
#pragma unroll
        for (int i = 0; i < 2; i++) {
            int idx = t * 2 + i;
            int kk = idx >> 5, n4 = idx & 31;
            *(float4*)&Bs[kk][n4 * 4] =
                *(const float4*)(B + (long long)(k0 + kk) * Nn + col0 + n4 * 4);
        }
        __syncthreads();
#pragma unroll
        for (int kk = 0; kk < 16; kk++) {
            float a[8], b[8];
            *(float4*)(a)     = *(float4*)&As[kk][ty * 8];
            *(float4*)(a + 4) = *(float4*)&As[kk][ty * 8 + 4];
            *(float4*)(b)     = *(float4*)&Bs[kk][tx * 8];
            *(float4*)(b + 4) = *(float4*)&Bs[kk][tx * 8 + 4];
#pragma unroll
            for (int i = 0; i < 8; i++)
#pragma unroll
                for (int j = 0; j < 8; j++) acc[i][j] += a[i] * b[j];
        }
        __syncthreads();
    }
#pragma unroll
    for (int i = 0; i < 8; i++) {
        int gr = row0 + ty * 8 + i;
        if (gr < M) {
            float* cp = Cc + (long long)gr * Nn + col0 + tx * 8;
            *(float4*)(cp)     = *(float4*)&acc[i][0];
            *(float4*)(cp + 4) = *(float4*)&acc[i][4];
        }
    }
}

// ------------------------- fused per-node attention (online softmax) --------
// Warp per destination node, SINGLE pass over incoming CSR edges:
// logit -> running-max rescale -> accumulate (xl reused from the logit load).
// Lane holds channels (lane&7)*4..+3 of head lane>>3 (o0) and (lane>>3)+4 (o1).
__device__ __forceinline__ void gat_core(int n, int lane, const float4* att4,
                                         float4& o0, float4& o1) {
    int beg = g_off[n], end = g_off[n + 1];
    const float4* xr4 = (const float4*)(g_xr + (long long)n * HC_);
    float4 r0 = xr4[lane], r1 = xr4[lane + 32];
    float4 a0 = att4[lane], a1 = att4[lane + 32];
    float mx0 = -3.4e38f, mx1 = -3.4e38f;
    float den0 = 0.f, den1 = 0.f;
    float4 ac0 = make_float4(0.f, 0.f, 0.f, 0.f);
    float4 ac1 = make_float4(0.f, 0.f, 0.f, 0.f);
    for (int i = beg; i < end; i++) {
        int s = g_esrc[i];
        const float4* xl4 = (const float4*)(g_xl + (long long)s * HC_);
        float4 l0 = xl4[lane], l1 = xl4[lane + 32];
        float v, s0 = 0.f, s1 = 0.f;
        v = l0.x + r0.x; v = (v > 0.f) ? v : SLOPE_ * v; s0 += v * a0.x;
        v = l0.y + r0.y; v = (v > 0.f) ? v : SLOPE_ * v; s0 += v * a0.y;
        v = l0.z + r0.z; v = (v > 0.f) ? v : SLOPE_ * v; s0 += v * a0.z;
        v = l0.w + r0.w; v = (v > 0.f) ? v : SLOPE_ * v; s0 += v * a0.w;
        v = l1.x + r1.x; v = (v > 0.f) ? v : SLOPE_ * v; s1 += v * a1.x;
        v = l1.y + r1.y; v = (v > 0.f) ? v : SLOPE_ * v; s1 += v * a1.y;
        v = l1.z + r1.z; v = (v > 0.f) ? v : SLOPE_ * v; s1 += v * a1.z;
        v = l1.w + r1.w; v = (v > 0.f) ? v : SLOPE_ * v; s1 += v * a1.w;
#pragma unroll
        for (int off = 4; off; off >>= 1) {
            s0 += __shfl_xor_sync(0xffffffffu, s0, off);
            s1 += __shfl_xor_sync(0xffffffffu, s1, off);
        }
        // online softmax update, head group 0 (all 8 lanes of a group agree)
        float nm0 = fmaxf(mx0, s0);
        float c0 = __expf(mx0 - nm0);     // 0 on first edge, 1 if no new max
        float w0 = __expf(s0 - nm0);
        mx0 = nm0;
        den0 = den0 * c0 + w0;
        ac0.x = ac0.x * c0 + w0 * l0.x;
        ac0.y = ac0.y * c0 + w0 * l0.y;
        ac0.z = ac0.z * c0 + w0 * l0.z;
        ac0.w = ac0.w * c0 + w0 * l0.w;
        // head group 1
        float nm1 = fmaxf(mx1, s1);
        float c1 = __expf(mx1 - nm1);
        float w1 = __expf(s1 - nm1);
        mx1 = nm1;
        den1 = den1 * c1 + w1;
        ac1.x = ac1.x * c1 + w1 * l1.x;
        ac1.y = ac1.y * c1 + w1 * l1.y;
        ac1.z = ac1.z * c1 + w1 * l1.z;
        ac1.w = ac1.w * c1 + w1 * l1.w;
    }
    float i0 = 1.f / den0, i1 = 1.f / den1;
    o0 = make_float4(ac0.x * i0, ac0.y * i0, ac0.z * i0, ac0.w * i0);
    o1 = make_float4(ac1.x * i1, ac1.y * i1, ac1.z * i1, ac1.w * i1);
}

// layer 0: h = elu(bn(out + b0)), concat layout [N, 256]
__global__ void gat_layer0(const float* __restrict__ att,
                           const float* __restrict__ b0, const float* __restrict__ g0,
                           const float* __restrict__ be0, const float* __restrict__ m0,
                           const float* __restrict__ v0, int N) {
    int lane = threadIdx.x & 31;
    int n = (blockIdx.x * blockDim.x + threadIdx.x) >> 5;
    if (n >= N) return;
    float4 o0, o1;
    gat_core(n, lane, (const float4*)att, o0, o1);
    float4* ph = (float4*)(g_h + (long long)n * HC_);
    float out[8] = {o0.x, o0.y, o0.z, o0.w, o1.x, o1.y, o1.z, o1.w};
#pragma unroll
    for (int half = 0; half < 2; half++) {
        int q = lane + half * 32;
        float4 bb = ((const float4*)b0)[q];
        float4 gg = ((const float4*)g0)[q];
        float4 be = ((const float4*)be0)[q];
        float4 mm = ((const float4*)m0)[q];
        float4 vv = ((const float4*)v0)[q];
        float r[4];
        float xb[4] = {out[half*4+0] + bb.x, out[half*4+1] + bb.y,
                       out[half*4+2] + bb.z, out[half*4+3] + bb.w};
        float mu[4] = {mm.x, mm.y, mm.z, mm.w};
        float va[4] = {vv.x, vv.y, vv.z, vv.w};
        float ga[4] = {gg.x, gg.y, gg.z, gg.w};
        float ba[4] = {be.x, be.y, be.z, be.w};
#pragma unroll
        for (int j = 0; j < 4; j++) {
            float xv = (xb[j] - mu[j]) * rsqrtf(va[j] + EPS_) * ga[j] + ba[j];
            r[j] = (xv > 0.f) ? xv : (__expf(xv) - 1.f);
        }
        ph[q] = make_float4(r[0], r[1], r[2], r[3]);
    }
}

// layer 1: s = bn(mean_h(out) + b1); y = s @ Wc + bc  -> out [N, 2]
__global__ void gat_layer1(const float* __restrict__ att,
                           const float* __restrict__ b1, const float* __restrict__ g1,
                           const float* __restrict__ be1, const float* __restrict__ m1,
                           const float* __restrict__ v1, const float* __restrict__ Wc,
                           const float* __restrict__ bc, float* __restrict__ outp, int N) {
    int lane = threadIdx.x & 31;
    int n = (blockIdx.x * blockDim.x + threadIdx.x) >> 5;
    if (n >= N) return;
    float4 o0, o1;
    gat_core(n, lane, (const float4*)att, o0, o1);
    // sum over 8 heads: o0 covers head lane>>3, o1 head (lane>>3)+4
    float t0 = o0.x + o1.x, t1 = o0.y + o1.y, t2 = o0.z + o1.z, t3 = o0.w + o1.w;
#pragma unroll
    for (int off = 8; off <= 16; off <<= 1) {
        t0 += __shfl_xor_sync(0xffffffffu, t0, off);
        t1 += __shfl_xor_sync(0xffffffffu, t1, off);
        t2 += __shfl_xor_sync(0xffffffffu, t2, off);
        t3 += __shfl_xor_sync(0xffffffffu, t3, off);
    }
    int cg = lane & 7;      // channel group: channels cg*4..cg*4+3
    float4 bb = ((const float4*)b1)[cg];
    float4 gg = ((const float4*)g1)[cg];
    float4 be = ((const float4*)be1)[cg];
    float4 mm = ((const float4*)m1)[cg];
    float4 vv = ((const float4*)v1)[cg];
    float s0 = (t0 * 0.125f + bb.x - mm.x) * rsqrtf(vv.x + EPS_) * gg.x + be.x;
    float s1 = (t1 * 0.125f + bb.y - mm.y) * rsqrtf(vv.y + EPS_) * gg.y + be.y;
    float s2 = (t2 * 0.125f + bb.z - mm.z) * rsqrtf(vv.z + EPS_) * gg.z + be.z;
    float s3 = (t3 * 0.125f + bb.w - mm.w) * rsqrtf(vv.w + EPS_) * gg.w + be.w;
    int c0 = cg * 4;
    float y0 = s0 * Wc[(c0+0)*2] + s1 * Wc[(c0+1)*2] + s2 * Wc[(c0+2)*2] + s3 * Wc[(c0+3)*2];
    float y1 = s0 * Wc[(c0+0)*2+1] + s1 * Wc[(c0+1)*2+1] + s2 * Wc[(c0+2)*2+1] + s3 * Wc[(c0+3)*2+1];
#pragma unroll
    for (int off = 4; off; off >>= 1) {
        y0 += __shfl_xor_sync(0xffffffffu, y0, off);
        y1 += __shfl_xor_sync(0xffffffffu, y1, off);
    }
    if (lane == 0) {
        outp[(long long)n * 2 + 0] = y0 + bc[0];
        outp[(long long)n * 2 + 1] = y1 + bc[1];
    }
}

// ---------------------------------------------------------------------------
extern "C" void kernel_launch(void* const* d_in, const int* in_sizes, int n_in,
                              void* d_out, int out_size) {
    const float* x    = (const float*)d_in[0];
    const void*  ei   = d_in[1];
    const float* Wl0  = (const float*)d_in[2];
    const float* Wr0  = (const float*)d_in[3];
    const float* att0 = (const float*)d_in[4];
    const float* b0   = (const float*)d_in[5];
    const float* g0   = (const float*)d_in[6];
    const float* be0  = (const float*)d_in[7];
    const float* m0   = (const float*)d_in[8];
    const float* v0   = (const float*)d_in[9];
    const float* Wl1  = (const float*)d_in[10];
    const float* Wr1  = (const float*)d_in[11];
    const float* att1 = (const float*)d_in[12];
    const float* b1   = (const float*)d_in[13];
    const float* g1   = (const float*)d_in[14];
    const float* be1  = (const float*)d_in[15];
    const float* m1   = (const float*)d_in[16];
    const float* v1   = (const float*)d_in[17];
    const float* Wc   = (const float*)d_in[18];
    const float* bc   = (const float*)d_in[19];
    float* out = (float*)d_out;

    int IN = in_sizes[2] / HC_;       // 128
    int N  = in_sizes[0] / IN;        // 50000
    int E  = in_sizes[1] / 2;         // 800000
    int Etot = E + N;

    void *p_xl, *p_xr, *p_h, *p_cnt;
    cudaGetSymbolAddress(&p_xl,  g_xl);
    cudaGetSymbolAddress(&p_xr,  g_xr);
    cudaGetSymbolAddress(&p_h,   g_h);
    cudaGetSymbolAddress(&p_cnt, g_cnt);

    // Side stream for the CSR build, forked/joined with events so the whole
    // chain overlaps the layer-0 GEMMs inside the captured graph.
    // (Created per call and intentionally not destroyed: kernel_launch runs
    // only a handful of times — replays use the captured graph.)
    cudaStream_t s1;
    cudaStreamCreateWithFlags(&s1, cudaStreamNonBlocking);
    cudaEvent_t eFork, eJoin;
    cudaEventCreateWithFlags(&eFork, cudaEventDisableTiming);
    cudaEventCreateWithFlags(&eJoin, cudaEventDisableTiming);

    cudaEventRecord(eFork, 0);
    cudaStreamWaitEvent(s1, eFork, 0);

    // ---- CSR build on side stream ----
    k_detect<<<1, 1, 0, s1>>>((const int*)ei, E);
    k_convert<<<(2 * E + 255) / 256, 256, 0, s1>>>(ei, E);
    cudaMemsetAsync(p_cnt, 0, (size_t)N * sizeof(int), s1);
    k_hist<<<(Etot + 255) / 256, 256, 0, s1>>>(E, N);
    k_scan<<<1, 1024, 0, s1>>>(N);
    k_scatter<<<(Etot + 255) / 256, 256, 0, s1>>>(E, N);
    cudaEventRecord(eJoin, s1);

    dim3 ggrid(HC_ / 128, (N + 127) / 128, 2);
    int nodeBlocks = (N * 32 + 255) / 256;

    // ---------------- layer 0 (GEMMs overlap CSR build) ----------------
    sgemm128x2<<<ggrid, 256>>>(x, Wl0, Wr0, (float*)p_xl, (float*)p_xr, N, IN, HC_);
    cudaStreamWaitEvent(0, eJoin, 0);
    gat_layer0<<<nodeBlocks, 256>>>(att0, b0, g0, be0, m0, v0, N);

    // ---------------- layer 1 ----------------
    sgemm128x2<<<ggrid, 256>>>((const float*)p_h, Wl1, Wr1,
                               (float*)p_xl, (float*)p_xr, N, HC_, HC_);
    gat_layer1<<<nodeBlocks, 256>>>(att1, b1, g1, be1, m1, v1, Wc, bc, out, N);
}

// round 10
// speedup vs baseline: 1.8118x; 1.0875x over previous
#include <cuda_runtime.h>
#include <cuda_bf16.h>

// ---------------------------------------------------------------------------
// GATv2 (2 layers) + BN + ELU + linear classifier.
// N=50000, E=800000, IN=128, H=8, C=32, NC=2.
// CSR build (multi-block scan, hist fused into convert, overlapped with
// layer-0 GEMMs), warp-per-node ONLINE-softmax fused attention+epilogue,
// 128x128 SGEMM with paired-B launches (gridDim.z selects Wl/Wr).
// ---------------------------------------------------------------------------

#define NMAX 50000
#define EMAX 800000
#define H_ 8
#define C_ 32
#define HC_ 256       // H*C
#define ETOTMAX (EMAX + NMAX)
#define EPS_ 1e-5f
#define SLOPE_ 0.2f
#define SCAN_B 256
#define NBLK ((NMAX + SCAN_B - 1) / SCAN_B)   // 196

// ------------------------- static device scratch ---------------------------
__device__ float g_xl[(size_t)NMAX * HC_];
__device__ float g_xr[(size_t)NMAX * HC_];
__device__ float g_h [(size_t)NMAX * HC_];
__device__ int   g_src[EMAX];
__device__ int   g_dst[EMAX];
__device__ int   g_off[NMAX + 1];
__device__ int   g_cnt[NMAX];        // counts, then cursor
__device__ int   g_blk[NBLK];
__device__ int   g_esrc[ETOTMAX];    // CSR: src node per edge slot
__device__ int   g_is64;

// ------------------------- edge index conversion + histogram ----------------
__global__ void k_detect(const int* __restrict__ ei, int E) {
    int ok64 = 1;
    int limit = (E > 64) ? 64 : E;
    for (int i = 0; i < limit; i++) {
        if (ei[2 * i + 1] != 0) { ok64 = 0; break; }
    }
    g_is64 = ok64;
}

// converts AND histograms dst (self-loop +1 folded into the scan's load)
__global__ void k_convert(const void* __restrict__ ei, int E) {
    int i = blockIdx.x * blockDim.x + threadIdx.x;
    int tot = 2 * E;
    if (i >= tot) return;
    int v;
    if (g_is64) v = (int)((const long long*)ei)[i];
    else        v = ((const int*)ei)[i];
    if (i < E) g_src[i] = v;
    else {
        g_dst[i - E] = v;
        atomicAdd(&g_cnt[v], 1);
    }
}

// ------------------------- 3-phase multi-block scan -------------------------
__device__ __forceinline__ int block_incl_scan(int* sh, int t, int v) {
    sh[t] = v;
    __syncthreads();
#pragma unroll
    for (int off = 1; off < SCAN_B; off <<= 1) {
        int u = (t >= off) ? sh[t - off] : 0;
        __syncthreads();
        sh[t] += u;
        __syncthreads();
    }
    return sh[t];
}

__global__ void k_scan_a(int N) {
    __shared__ int sh[SCAN_B];
    int t = threadIdx.x;
    int i = blockIdx.x * SCAN_B + t;
    int c = (i < N) ? (g_cnt[i] + 1) : 0;       // +1 = self loop
    int incl = block_incl_scan(sh, t, c);
    if (i < N) {
        g_off[i + 1] = incl;          // block-local inclusive
        g_cnt[i] = incl - c;          // block-local exclusive (cursor base)
    }
    if (t == SCAN_B - 1) g_blk[blockIdx.x] = incl;
}

__global__ void k_scan_b(int nb) {
    __shared__ int sh[SCAN_B];
    int t = threadIdx.x;
    int v = (t < nb) ? g_blk[t] : 0;
    int incl = block_incl_scan(sh, t, v);
    if (t < nb) g_blk[t] = incl - v;            // exclusive block offset
}

__global__ void k_scan_c(int N) {
    int i = blockIdx.x * SCAN_B + threadIdx.x;
    int add = g_blk[blockIdx.x];
    if (i < N) {
        g_off[i + 1] += add;
        g_cnt[i] += add;
    }
    if (i == 0) g_off[0] = 0;
}

__global__ void k_scatter(int E, int N) {
    int i = blockIdx.x * blockDim.x + threadIdx.x;
    if (i < E) {
        int pos = atomicAdd(&g_cnt[g_dst[i]], 1);
        g_esrc[pos] = g_src[i];
    } else if (i < E + N) {
        int n = i - E;
        int pos = atomicAdd(&g_cnt[n], 1);
        g_esrc[pos] = n;
    }
}

// ------------------------- SGEMM pair: C[z] = A @ B[z] ----------------------
// 128x128 tile, 8x8 microtile, 256 threads, K-step 16. gridDim.z = 2 picks
// (B0->C0) or (B1->C1), so one launch does both the Wl and Wr projections.
__global__ void __launch_bounds__(256, 2)
sgemm128x2(const float* __restrict__ A,
           const float* __restrict__ B0, const float* __restrict__ B1,
           float* __restrict__ C0, float* __restrict__ C1,
           int M, int K, int Nn) {
    const float* B = (blockIdx.z == 0) ? B0 : B1;
    float*       Cc = (blockIdx.z == 0) ? C0 : C1;
    __shared__ float As[16][132];
    __shared__ float Bs[16][128];
    int t  = threadIdx.x;
    int tx = t & 15, ty = t >> 4;
    int row0 = blockIdx.y * 128, col0 = blockIdx.x * 128;
    float acc[8][8] = {};
    for (int k0 = 0; k0 < K; k0 += 16) {
#pragma unroll
        for (int i = 0; i < 2; i++) {
            int idx = t * 2 + i;          // 0..511
            int m = idx >> 2, kq = idx & 3;
            int gr = row0 + m;
            float4 v = make_float4(0.f, 0.f, 0.f, 0.f);
            if (gr < M) v = *(const float4*)(A + (long long)gr * K + k0 + kq * 4);
            As[kq * 4 + 0][m] = v.x;
            As[kq * 4 + 1][m] = v.y;
            As[kq * 4 + 2][m] = v.z;
            As[kq * 4 + 3][m] = v.w;
        }
#pragma unroll
        for (int i = 0; i < 2; i++) {
            int idx = t * 2 + i;
            int kk = idx >> 5, n4 = idx & 31;
            *(float4*)&Bs[kk][n4 * 4] =
                *(const float4*)(B + (long long)(k0 + kk) * Nn + col0 + n4 * 4);
        }
        __syncthreads();
#pragma unroll
        for (int kk = 0; kk < 16; kk++) {
            float a[8], b[8];
            *(float4*)(a)     = *(float4*)&As[kk][ty * 8];
            *(float4*)(a + 4) = *(float4*)&As[kk][ty * 8 + 4];
            *(float4*)(b)     = *(float4*)&Bs[kk][tx * 8];
            *(float4*)(b + 4) = *(float4*)&Bs[kk][tx * 8 + 4];
#pragma unroll
            for (int i = 0; i < 8; i++)
#pragma unroll
                for (int j = 0; j < 8; j++) acc[i][j] += a[i] * b[j];
        }
        __syncthreads();
    }
#pragma unroll
    for (int i = 0; i < 8; i++) {
        int gr = row0 + ty * 8 + i;
        if (gr < M) {
            float* cp = Cc + (long long)gr * Nn + col0 + tx * 8;
            *(float4*)(cp)     = *(float4*)&acc[i][0];
            *(float4*)(cp + 4) = *(float4*)&acc[i][4];
        }
    }
}

// ------------------------- fused per-node attention (online softmax) --------
// Warp per destination node, SINGLE pass over incoming CSR edges:
// logit -> running-max rescale -> accumulate (xl reused from the logit load).
// Lane holds channels (lane&7)*4..+3 of head lane>>3 (o0) and (lane>>3)+4 (o1).
__device__ __forceinline__ void gat_core(int n, int lane, const float4* att4,
                                         float4& o0, float4& o1) {
    int beg = g_off[n], end = g_off[n + 1];
    const float4* xr4 = (const float4*)(g_xr + (long long)n * HC_);
    float4 r0 = xr4[lane], r1 = xr4[lane + 32];
    float4 a0 = att4[lane], a1 = att4[lane + 32];
    float mx0 = -3.4e38f, mx1 = -3.4e38f;
    float den0 = 0.f, den1 = 0.f;
    float4 ac0 = make_float4(0.f, 0.f, 0.f, 0.f);
    float4 ac1 = make_float4(0.f, 0.f, 0.f, 0.f);
    for (int i = beg; i < end; i++) {
        int s = g_esrc[i];
        const float4* xl4 = (const float4*)(g_xl + (long long)s * HC_);
        float4 l0 = xl4[lane], l1 = xl4[lane + 32];
        float v, s0 = 0.f, s1 = 0.f;
        v = l0.x + r0.x; v = (v > 0.f) ? v : SLOPE_ * v; s0 += v * a0.x;
        v = l0.y + r0.y; v = (v > 0.f) ? v : SLOPE_ * v; s0 += v * a0.y;
        v = l0.z + r0.z; v = (v > 0.f) ? v : SLOPE_ * v; s0 += v * a0.z;
        v = l0.w + r0.w; v = (v > 0.f) ? v : SLOPE_ * v; s0 += v * a0.w;
        v = l1.x + r1.x; v = (v > 0.f) ? v : SLOPE_ * v; s1 += v * a1.x;
        v = l1.y + r1.y; v = (v > 0.f) ? v : SLOPE_ * v; s1 += v * a1.y;
        v = l1.z + r1.z; v = (v > 0.f) ? v : SLOPE_ * v; s1 += v * a1.z;
        v = l1.w + r1.w; v = (v > 0.f) ? v : SLOPE_ * v; s1 += v * a1.w;
#pragma unroll
        for (int off = 4; off; off >>= 1) {
            s0 += __shfl_xor_sync(0xffffffffu, s0, off);
            s1 += __shfl_xor_sync(0xffffffffu, s1, off);
        }
        // online softmax update, head group 0 (all 8 lanes of a group agree)
        float nm0 = fmaxf(mx0, s0);
        float c0 = __expf(mx0 - nm0);     // 0 on first edge, 1 if no new max
        float w0 = __expf(s0 - nm0);
        mx0 = nm0;
        den0 = den0 * c0 + w0;
        ac0.x = ac0.x * c0 + w0 * l0.x;
        ac0.y = ac0.y * c0 + w0 * l0.y;
        ac0.z = ac0.z * c0 + w0 * l0.z;
        ac0.w = ac0.w * c0 + w0 * l0.w;
        // head group 1
        float nm1 = fmaxf(mx1, s1);
        float c1 = __expf(mx1 - nm1);
        float w1 = __expf(s1 - nm1);
        mx1 = nm1;
        den1 = den1 * c1 + w1;
        ac1.x = ac1.x * c1 + w1 * l1.x;
        ac1.y = ac1.y * c1 + w1 * l1.y;
        ac1.z = ac1.z * c1 + w1 * l1.z;
        ac1.w = ac1.w * c1 + w1 * l1.w;
    }
    float i0 = 1.f / den0, i1 = 1.f / den1;
    o0 = make_float4(ac0.x * i0, ac0.y * i0, ac0.z * i0, ac0.w * i0);
    o1 = make_float4(ac1.x * i1, ac1.y * i1, ac1.z * i1, ac1.w * i1);
}

// layer 0: h = elu(bn(out + b0)), concat layout [N, 256]
__global__ void gat_layer0(const float* __restrict__ att,
                           const float* __restrict__ b0, const float* __restrict__ g0,
                           const float* __restrict__ be0, const float* __restrict__ m0,
                           const float* __restrict__ v0, int N) {
    int lane = threadIdx.x & 31;
    int n = (blockIdx.x * blockDim.x + threadIdx.x) >> 5;
    if (n >= N) return;
    float4 o0, o1;
    gat_core(n, lane, (const float4*)att, o0, o1);
    float4* ph = (float4*)(g_h + (long long)n * HC_);
    float out[8] = {o0.x, o0.y, o0.z, o0.w, o1.x, o1.y, o1.z, o1.w};
#pragma unroll
    for (int half = 0; half < 2; half++) {
        int q = lane + half * 32;
        float4 bb = ((const float4*)b0)[q];
        float4 gg = ((const float4*)g0)[q];
        float4 be = ((const float4*)be0)[q];
        float4 mm = ((const float4*)m0)[q];
        float4 vv = ((const float4*)v0)[q];
        float r[4];
        float xb[4] = {out[half*4+0] + bb.x, out[half*4+1] + bb.y,
                       out[half*4+2] + bb.z, out[half*4+3] + bb.w};
        float mu[4] = {mm.x, mm.y, mm.z, mm.w};
        float va[4] = {vv.x, vv.y, vv.z, vv.w};
        float ga[4] = {gg.x, gg.y, gg.z, gg.w};
        float ba[4] = {be.x, be.y, be.z, be.w};
#pragma unroll
        for (int j = 0; j < 4; j++) {
            float xv = (xb[j] - mu[j]) * rsqrtf(va[j] + EPS_) * ga[j] + ba[j];
            r[j] = (xv > 0.f) ? xv : (__expf(xv) - 1.f);
        }
        ph[q] = make_float4(r[0], r[1], r[2], r[3]);
    }
}

// layer 1: s = bn(mean_h(out) + b1); y = s @ Wc + bc  -> out [N, 2]
__global__ void gat_layer1(const float* __restrict__ att,
                           const float* __restrict__ b1, const float* __restrict__ g1,
                           const float* __restrict__ be1, const float* __restrict__ m1,
                           const float* __restrict__ v1, const float* __restrict__ Wc,
                           const float* __restrict__ bc, float* __restrict__ outp, int N) {
    int lane = threadIdx.x & 31;
    int n = (blockIdx.x * blockDim.x + threadIdx.x) >> 5;
    if (n >= N) return;
    float4 o0, o1;
    gat_core(n, lane, (const float4*)att, o0, o1);
    // sum over 8 heads: o0 covers head lane>>3, o1 head (lane>>3)+4
    float t0 = o0.x + o1.x, t1 = o0.y + o1.y, t2 = o0.z + o1.z, t3 = o0.w + o1.w;
#pragma unroll
    for (int off = 8; off <= 16; off <<= 1) {
        t0 += __shfl_xor_sync(0xffffffffu, t0, off);
        t1 += __shfl_xor_sync(0xffffffffu, t1, off);
        t2 += __shfl_xor_sync(0xffffffffu, t2, off);
        t3 += __shfl_xor_sync(0xffffffffu, t3, off);
    }
    int cg = lane & 7;      // channel group: channels cg*4..cg*4+3
    float4 bb = ((const float4*)b1)[cg];
    float4 gg = ((const float4*)g1)[cg];
    float4 be = ((const float4*)be1)[cg];
    float4 mm = ((const float4*)m1)[cg];
    float4 vv = ((const float4*)v1)[cg];
    float s0 = (t0 * 0.125f + bb.x - mm.x) * rsqrtf(vv.x + EPS_) * gg.x + be.x;
    float s1 = (t1 * 0.125f + bb.y - mm.y) * rsqrtf(vv.y + EPS_) * gg.y + be.y;
    float s2 = (t2 * 0.125f + bb.z - mm.z) * rsqrtf(vv.z + EPS_) * gg.z + be.z;
    float s3 = (t3 * 0.125f + bb.w - mm.w) * rsqrtf(vv.w + EPS_) * gg.w + be.w;
    int c0 = cg * 4;
    float y0 = s0 * Wc[(c0+0)*2] + s1 * Wc[(c0+1)*2] + s2 * Wc[(c0+2)*2] + s3 * Wc[(c0+3)*2];
    float y1 = s0 * Wc[(c0+0)*2+1] + s1 * Wc[(c0+1)*2+1] + s2 * Wc[(c0+2)*2+1] + s3 * Wc[(c0+3)*2+1];
#pragma unroll
    for (int off = 4; off; off >>= 1) {
        y0 += __shfl_xor_sync(0xffffffffu, y0, off);
        y1 += __shfl_xor_sync(0xffffffffu, y1, off);
    }
    if (lane == 0) {
        outp[(long long)n * 2 + 0] = y0 + bc[0];
        outp[(long long)n * 2 + 1] = y1 + bc[1];
    }
}

// ---------------------------------------------------------------------------
extern "C" void kernel_launch(void* const* d_in, const int* in_sizes, int n_in,
                              void* d_out, int out_size) {
    const float* x    = (const float*)d_in[0];
    const void*  ei   = d_in[1];
    const float* Wl0  = (const float*)d_in[2];
    const float* Wr0  = (const float*)d_in[3];
    const float* att0 = (const float*)d_in[4];
    const float* b0   = (const float*)d_in[5];
    const float* g0   = (const float*)d_in[6];
    const float* be0  = (const float*)d_in[7];
    const float* m0   = (const float*)d_in[8];
    const float* v0   = (const float*)d_in[9];
    const float* Wl1  = (const float*)d_in[10];
    const float* Wr1  = (const float*)d_in[11];
    const float* att1 = (const float*)d_in[12];
    const float* b1   = (const float*)d_in[13];
    const float* g1   = (const float*)d_in[14];
    const float* be1  = (const float*)d_in[15];
    const float* m1   = (const float*)d_in[16];
    const float* v1   = (const float*)d_in[17];
    const float* Wc   = (const float*)d_in[18];
    const float* bc   = (const float*)d_in[19];
    float* out = (float*)d_out;

    int IN = in_sizes[2] / HC_;       // 128
    int N  = in_sizes[0] / IN;        // 50000
    int E  = in_sizes[1] / 2;         // 800000
    int Etot = E + N;
    int nb = (N + SCAN_B - 1) / SCAN_B;

    void *p_xl, *p_xr, *p_h, *p_cnt;
    cudaGetSymbolAddress(&p_xl,  g_xl);
    cudaGetSymbolAddress(&p_xr,  g_xr);
    cudaGetSymbolAddress(&p_h,   g_h);
    cudaGetSymbolAddress(&p_cnt, g_cnt);

    // Side stream for the CSR build, forked/joined with events so the whole
    // chain overlaps the layer-0 GEMMs inside the captured graph.
    cudaStream_t s1;
    cudaStreamCreateWithFlags(&s1, cudaStreamNonBlocking);
    cudaEvent_t eFork, eJoin;
    cudaEventCreateWithFlags(&eFork, cudaEventDisableTiming);
    cudaEventCreateWithFlags(&eJoin, cudaEventDisableTiming);

    cudaEventRecord(eFork, 0);
    cudaStreamWaitEvent(s1, eFork, 0);

    // ---- CSR build on side stream ----
    k_detect<<<1, 1, 0, s1>>>((const int*)ei, E);
    cudaMemsetAsync(p_cnt, 0, (size_t)N * sizeof(int), s1);
    k_convert<<<(2 * E + 255) / 256, 256, 0, s1>>>(ei, E);   // + dst histogram
    k_scan_a<<<nb, SCAN_B, 0, s1>>>(N);
    k_scan_b<<<1, SCAN_B, 0, s1>>>(nb);
    k_scan_c<<<nb, SCAN_B, 0, s1>>>(N);
    k_scatter<<<(Etot + 255) / 256, 256, 0, s1>>>(E, N);
    cudaEventRecord(eJoin, s1);

    dim3 ggrid(HC_ / 128, (N + 127) / 128, 2);
    int nodeBlocks = (N * 32 + 255) / 256;

    // ---------------- layer 0 (GEMMs overlap CSR build) ----------------
    sgemm128x2<<<ggrid, 256>>>(x, Wl0, Wr0, (float*)p_xl, (float*)p_xr, N, IN, HC_);
    cudaStreamWaitEvent(0, eJoin, 0);
    gat_layer0<<<nodeBlocks, 256>>>(att0, b0, g0, be0, m0, v0, N);

    // ---------------- layer 1 ----------------
    sgemm128x2<<<ggrid, 256>>>((const float*)p_h, Wl1, Wr1,
                               (float*)p_xl, (float*)p_xr, N, HC_, HC_);
    gat_layer1<<<nodeBlocks, 256>>>(att1, b1, g1, be1, m1, v1, Wc, bc, out, N);
}

// round 12
// speedup vs baseline: 2.9476x; 1.6269x over previous
#include <cuda_runtime.h>
#include <cuda_bf16.h>
#include <cstdint>

// ---------------------------------------------------------------------------
// GATv2 (2 layers) + BN + ELU + linear classifier.
// N=50000, E=800000, IN=128, H=8, C=32, NC=2.
// GEMMs on mma.sync.m16n8k16 bf16 (HMMA, plain sm_80 PTX — works on the
// harness's non-'a' ptx target) with K-concatenated hi/lo split for fp32-level
// accuracy. CSR build overlapped; warp-per-node online-softmax attention.
// ---------------------------------------------------------------------------

#define NMAX 50000
#define EMAX 800000
#define H_ 8
#define C_ 32
#define HC_ 256       // H*C
#define ETOTMAX (EMAX + NMAX)
#define EPS_ 1e-5f
#define SLOPE_ 0.2f
#define SCAN_B 256
#define NBLK ((NMAX + SCAN_B - 1) / SCAN_B)

// ------------------------- static device scratch ---------------------------
__device__ float g_xl[(size_t)NMAX * HC_];
__device__ float g_xr[(size_t)NMAX * HC_];
// A operand, hi|lo concatenated along K. Layer 0: pitch 256 (x split).
// Layer 1: pitch 512 (h split). Same buffer, different pitch.
__device__ __align__(16) __nv_bfloat16 g_a2[(size_t)NMAX * 512];
// Transposed weights, hi|lo concatenated along K.
// Slots 0/1: layer-0 Wl/Wr [256 rows][256]; slots 2/3: layer-1 [256][512].
__device__ __align__(16) __nv_bfloat16 g_w2[4][256 * 512];
__device__ int   g_src[EMAX];
__device__ int   g_dst[EMAX];
__device__ int   g_off[NMAX + 1];
__device__ int   g_cnt[NMAX];
__device__ int   g_blk[NBLK];
__device__ int   g_esrc[ETOTMAX];
__device__ int   g_is64;

// ------------------------- PTX helpers --------------------------------------
__device__ __forceinline__ uint32_t smem_to_u32(const void* p) {
    uint32_t a;
    asm("{ .reg .u64 t; cvta.to.shared.u64 t, %1; cvt.u32.u64 %0, t; }"
        : "=r"(a) : "l"(p));
    return a;
}
__device__ __forceinline__ void ldsm4(uint32_t* r, uint32_t addr) {
    asm volatile("ldmatrix.sync.aligned.m8n8.x4.shared.b16 {%0,%1,%2,%3}, [%4];"
                 : "=r"(r[0]), "=r"(r[1]), "=r"(r[2]), "=r"(r[3]) : "r"(addr));
}
__device__ __forceinline__ void mma16816(float* c, const uint32_t* a, const uint32_t* b) {
    asm volatile("mma.sync.aligned.m16n8k16.row.col.f32.bf16.bf16.f32 "
                 "{%0,%1,%2,%3}, {%4,%5,%6,%7}, {%8,%9}, {%0,%1,%2,%3};"
                 : "+f"(c[0]), "+f"(c[1]), "+f"(c[2]), "+f"(c[3])
                 : "r"(a[0]), "r"(a[1]), "r"(a[2]), "r"(a[3]),
                   "r"(b[0]), "r"(b[1]));
}

// ------------------------- edge index conversion + histogram ----------------
__global__ void k_detect(const int* __restrict__ ei, int E) {
    int ok64 = 1;
    int limit = (E > 64) ? 64 : E;
    for (int i = 0; i < limit; i++)
        if (ei[2 * i + 1] != 0) { ok64 = 0; break; }
    g_is64 = ok64;
}

__global__ void k_convert(const void* __restrict__ ei, int E) {
    int i = blockIdx.x * blockDim.x + threadIdx.x;
    int tot = 2 * E;
    if (i >= tot) return;
    int v;
    if (g_is64) v = (int)((const long long*)ei)[i];
    else        v = ((const int*)ei)[i];
    if (i < E) g_src[i] = v;
    else {
        g_dst[i - E] = v;
        atomicAdd(&g_cnt[v], 1);
    }
}

// ------------------------- 3-phase multi-block scan -------------------------
__device__ __forceinline__ int block_incl_scan(int* sh, int t, int v) {
    sh[t] = v;
    __syncthreads();
#pragma unroll
    for (int off = 1; off < SCAN_B; off <<= 1) {
        int u = (t >= off) ? sh[t - off] : 0;
        __syncthreads();
        sh[t] += u;
        __syncthreads();
    }
    return sh[t];
}

__global__ void k_scan_a(int N) {
    __shared__ int sh[SCAN_B];
    int t = threadIdx.x;
    int i = blockIdx.x * SCAN_B + t;
    int c = (i < N) ? (g_cnt[i] + 1) : 0;
    int incl = block_incl_scan(sh, t, c);
    if (i < N) {
        g_off[i + 1] = incl;
        g_cnt[i] = incl - c;
    }
    if (t == SCAN_B - 1) g_blk[blockIdx.x] = incl;
}

__global__ void k_scan_b(int nb) {
    __shared__ int sh[SCAN_B];
    int t = threadIdx.x;
    int v = (t < nb) ? g_blk[t] : 0;
    int incl = block_incl_scan(sh, t, v);
    if (t < nb) g_blk[t] = incl - v;
}

__global__ void k_scan_c(int N) {
    int i = blockIdx.x * SCAN_B + threadIdx.x;
    int add = g_blk[blockIdx.x];
    if (i < N) {
        g_off[i + 1] += add;
        g_cnt[i] += add;
    }
    if (i == 0) g_off[0] = 0;
}

__global__ void k_scatter(int E, int N) {
    int i = blockIdx.x * blockDim.x + threadIdx.x;
    if (i < E) {
        int pos = atomicAdd(&g_cnt[g_dst[i]], 1);
        g_esrc[pos] = g_src[i];
    } else if (i < E + N) {
        int n = i - E;
        int pos = atomicAdd(&g_cnt[n], 1);
        g_esrc[pos] = n;
    }
}

// ------------------------- bf16 split prep ----------------------------------
// x [N, 128] fp32 -> g_a2 [N, 256]: cols 0-127 hi, 128-255 lo
__global__ void k_split_x(const float* __restrict__ x, int total4) {
    int i = blockIdx.x * blockDim.x + threadIdx.x;
    if (i >= total4) return;
    float4 v = ((const float4*)x)[i];
    float f[4] = {v.x, v.y, v.z, v.w};
    __nv_bfloat16 h[4]; float l[4];
#pragma unroll
    for (int j = 0; j < 4; j++) {
        h[j] = __float2bfloat16(f[j]);
        l[j] = f[j] - __bfloat162float(h[j]);
    }
    uint2 uh, ul;
    ((__nv_bfloat162*)&uh)[0] = __nv_bfloat162(h[0], h[1]);
    ((__nv_bfloat162*)&uh)[1] = __nv_bfloat162(h[2], h[3]);
    ((__nv_bfloat162*)&ul)[0] = __floats2bfloat162_rn(l[0], l[1]);
    ((__nv_bfloat162*)&ul)[1] = __floats2bfloat162_rn(l[2], l[3]);
    int e = i * 4;
    int row = e >> 7, col = e & 127;          // IN = 128
    *(uint2*)(g_a2 + (size_t)row * 256 + col)       = uh;
    *(uint2*)(g_a2 + (size_t)row * 256 + 128 + col) = ul;
}

// W [K, Nn] fp32 -> out [Nn, 2K]: out[n][k]=hi, out[n][K+k]=lo (transposed)
__global__ void k_split_w(const float* __restrict__ W, __nv_bfloat16* __restrict__ o,
                          int K, int Nn) {
    int i = blockIdx.x * blockDim.x + threadIdx.x;
    if (i >= K * Nn) return;
    int k = i / Nn, n = i % Nn;
    float w = W[i];
    __nv_bfloat16 h = __float2bfloat16(w);
    o[(size_t)n * 2 * K + k]     = h;
    o[(size_t)n * 2 * K + K + k] = __float2bfloat16(w - __bfloat162float(h));
}

// ------------------------- HMMA GEMM pair -----------------------------------
// C[z][M,Nn] = A2[M,K2] @ W2t[z][Nn,K2]^T  (bf16 in, fp32 out; K2 = 2K split).
// 128x128 CTA tile, 8 warps (4M x 2N), warp tile 32x64, BK=32.
#define BM 128
#define BN 128
#define BK 32
#define APAD 8
#define LDT (BK + APAD)    // 40 bf16

__global__ void __launch_bounds__(256, 2)
hmma_gemm(const __nv_bfloat16* __restrict__ A2,
          const __nv_bfloat16* __restrict__ B0t, const __nv_bfloat16* __restrict__ B1t,
          float* __restrict__ C0, float* __restrict__ C1,
          int M, int K2, int Nn) {
    const __nv_bfloat16* Bt = (blockIdx.z == 0) ? B0t : B1t;
    float* Cc = (blockIdx.z == 0) ? C0 : C1;
    __shared__ __align__(16) __nv_bfloat16 As[BM][LDT];
    __shared__ __align__(16) __nv_bfloat16 Bs[BN][LDT];
    int tid = threadIdx.x;
    int lane = tid & 31, warp = tid >> 5;
    int wm = warp & 3, wn = warp >> 2;        // 4 x 2 warp grid
    int rowBase = blockIdx.y * BM;
    int colBase = blockIdx.x * BN;
    uint32_t sA = smem_to_u32(As), sB = smem_to_u32(Bs);

    float c[2][8][4];
#pragma unroll
    for (int a = 0; a < 2; a++)
#pragma unroll
        for (int b = 0; b < 8; b++)
#pragma unroll
            for (int d = 0; d < 4; d++) c[a][b][d] = 0.f;

    // ldmatrix source addresses (fixed per lane)
    int aRow = wm * 32 + (lane & 15);
    int aColOff = (lane >> 4) << 3;
    int bRow = wn * 64 + ((lane >> 4) << 3) + (lane & 7);
    int bColOff = ((lane >> 3) & 1) << 3;

    for (int k0 = 0; k0 < K2; k0 += BK) {
#pragma unroll
        for (int j = 0; j < 2; j++) {
            int i = tid + j * 256;            // 0..511
            int row = i >> 2, q = i & 3;
            int gr = rowBase + row;
            uint4 va = make_uint4(0, 0, 0, 0);
            if (gr < M) va = *(const uint4*)(A2 + (size_t)gr * K2 + k0 + q * 8);
            *(uint4*)&As[row][q * 8] = va;
            *(uint4*)&Bs[row][q * 8] =
                *(const uint4*)(Bt + (size_t)(colBase + row) * K2 + k0 + q * 8);
        }
        __syncthreads();
#pragma unroll
        for (int kk = 0; kk < BK; kk += 16) {
            uint32_t af[2][4];
#pragma unroll
            for (int mi = 0; mi < 2; mi++)
                ldsm4(af[mi], sA + ((aRow + mi * 16) * LDT + kk + aColOff) * 2);
#pragma unroll
            for (int ni = 0; ni < 4; ni++) {
                uint32_t bf[4];
                ldsm4(bf, sB + ((bRow + ni * 16) * LDT + kk + bColOff) * 2);
#pragma unroll
                for (int mi = 0; mi < 2; mi++) {
                    mma16816(c[mi][ni * 2 + 0], af[mi], bf);
                    mma16816(c[mi][ni * 2 + 1], af[mi], bf + 2);
                }
            }
        }
        __syncthreads();
    }

    // epilogue: fragment (mi, ni): rows rowBase+wm*32+mi*16+{lane>>2, +8},
    // cols colBase+wn*64+ni*8+(lane&3)*2
    int r0 = rowBase + wm * 32 + (lane >> 2);
    int cg0 = colBase + wn * 64 + (lane & 3) * 2;
#pragma unroll
    for (int mi = 0; mi < 2; mi++) {
#pragma unroll
        for (int ni = 0; ni < 8; ni++) {
            int row = r0 + mi * 16;
            int col = cg0 + ni * 8;
            if (row < M)
                *(float2*)(Cc + (size_t)row * Nn + col) =
                    make_float2(c[mi][ni][0], c[mi][ni][1]);
            if (row + 8 < M)
                *(float2*)(Cc + (size_t)(row + 8) * Nn + col) =
                    make_float2(c[mi][ni][2], c[mi][ni][3]);
        }
    }
}

// ------------------------- fused per-node attention (online softmax) --------
__device__ __forceinline__ void gat_core(int n, int lane, const float4* att4,
                                         float4& o0, float4& o1) {
    int beg = g_off[n], end = g_off[n + 1];
    const float4* xr4 = (const float4*)(g_xr + (long long)n * HC_);
    float4 r0 = xr4[lane], r1 = xr4[lane + 32];
    float4 a0 = att4[lane], a1 = att4[lane + 32];
    float mx0 = -3.4e38f, mx1 = -3.4e38f;
    float den0 = 0.f, den1 = 0.f;
    float4 ac0 = make_float4(0.f, 0.f, 0.f, 0.f);
    float4 ac1 = make_float4(0.f, 0.f, 0.f, 0.f);
    for (int i = beg; i < end; i++) {
        int s = g_esrc[i];
        const float4* xl4 = (const float4*)(g_xl + (long long)s * HC_);
        float4 l0 = xl4[lane], l1 = xl4[lane + 32];
        float v, s0 = 0.f, s1 = 0.f;
        v = l0.x + r0.x; v = (v > 0.f) ? v : SLOPE_ * v; s0 += v * a0.x;
        v = l0.y + r0.y; v = (v > 0.f) ? v : SLOPE_ * v; s0 += v * a0.y;
        v = l0.z + r0.z; v = (v > 0.f) ? v : SLOPE_ * v; s0 += v * a0.z;
        v = l0.w + r0.w; v = (v > 0.f) ? v : SLOPE_ * v; s0 += v * a0.w;
        v = l1.x + r1.x; v = (v > 0.f) ? v : SLOPE_ * v; s1 += v * a1.x;
        v = l1.y + r1.y; v = (v > 0.f) ? v : SLOPE_ * v; s1 += v * a1.y;
        v = l1.z + r1.z; v = (v > 0.f) ? v : SLOPE_ * v; s1 += v * a1.z;
        v = l1.w + r1.w; v = (v > 0.f) ? v : SLOPE_ * v; s1 += v * a1.w;
#pragma unroll
        for (int off = 4; off; off >>= 1) {
            s0 += __shfl_xor_sync(0xffffffffu, s0, off);
            s1 += __shfl_xor_sync(0xffffffffu, s1, off);
        }
        float nm0 = fmaxf(mx0, s0);
        float c0 = __expf(mx0 - nm0);
        float w0 = __expf(s0 - nm0);
        mx0 = nm0;
        den0 = den0 * c0 + w0;
        ac0.x = ac0.x * c0 + w0 * l0.x;
        ac0.y = ac0.y * c0 + w0 * l0.y;
        ac0.z = ac0.z * c0 + w0 * l0.z;
        ac0.w = ac0.w * c0 + w0 * l0.w;
        float nm1 = fmaxf(mx1, s1);
        float c1 = __expf(mx1 - nm1);
        float w1 = __expf(s1 - nm1);
        mx1 = nm1;
        den1 = den1 * c1 + w1;
        ac1.x = ac1.x * c1 + w1 * l1.x;
        ac1.y = ac1.y * c1 + w1 * l1.y;
        ac1.z = ac1.z * c1 + w1 * l1.z;
        ac1.w = ac1.w * c1 + w1 * l1.w;
    }
    float i0 = 1.f / den0, i1 = 1.f / den1;
    o0 = make_float4(ac0.x * i0, ac0.y * i0, ac0.z * i0, ac0.w * i0);
    o1 = make_float4(ac1.x * i1, ac1.y * i1, ac1.z * i1, ac1.w * i1);
}

// layer 0: h = elu(bn(out + b0)) -> hi/lo K-concat split into g_a2 [N, 512]
__global__ void gat_layer0(const float* __restrict__ att,
                           const float* __restrict__ b0, const float* __restrict__ g0,
                           const float* __restrict__ be0, const float* __restrict__ m0,
                           const float* __restrict__ v0, int N) {
    int lane = threadIdx.x & 31;
    int n = (blockIdx.x * blockDim.x + threadIdx.x) >> 5;
    if (n >= N) return;
    float4 o0, o1;
    gat_core(n, lane, (const float4*)att, o0, o1);
    float out[8] = {o0.x, o0.y, o0.z, o0.w, o1.x, o1.y, o1.z, o1.w};
    __nv_bfloat16* ah = g_a2 + (size_t)n * 512;
#pragma unroll
    for (int half = 0; half < 2; half++) {
        int q = lane + half * 32;
        float4 bb = ((const float4*)b0)[q];
        float4 gg = ((const float4*)g0)[q];
        float4 be = ((const float4*)be0)[q];
        float4 mm = ((const float4*)m0)[q];
        float4 vv = ((const float4*)v0)[q];
        float xb[4] = {out[half*4+0] + bb.x, out[half*4+1] + bb.y,
                       out[half*4+2] + bb.z, out[half*4+3] + bb.w};
        float mu[4] = {mm.x, mm.y, mm.z, mm.w};
        float va[4] = {vv.x, vv.y, vv.z, vv.w};
        float ga[4] = {gg.x, gg.y, gg.z, gg.w};
        float ba[4] = {be.x, be.y, be.z, be.w};
        __nv_bfloat16 rh[4]; float rl[4];
#pragma unroll
        for (int j = 0; j < 4; j++) {
            float xv = (xb[j] - mu[j]) * rsqrtf(va[j] + EPS_) * ga[j] + ba[j];
            float r = (xv > 0.f) ? xv : (__expf(xv) - 1.f);
            rh[j] = __float2bfloat16(r);
            rl[j] = r - __bfloat162float(rh[j]);
        }
        uint2 uh, ul;
        ((__nv_bfloat162*)&uh)[0] = __nv_bfloat162(rh[0], rh[1]);
        ((__nv_bfloat162*)&uh)[1] = __nv_bfloat162(rh[2], rh[3]);
        ((__nv_bfloat162*)&ul)[0] = __floats2bfloat162_rn(rl[0], rl[1]);
        ((__nv_bfloat162*)&ul)[1] = __floats2bfloat162_rn(rl[2], rl[3]);
        *(uint2*)(ah + q * 4)       = uh;
        *(uint2*)(ah + 256 + q * 4) = ul;
    }
}

// layer 1: s = bn(mean_h(out) + b1); y = s @ Wc + bc  -> out [N, 2]
__global__ void gat_layer1(const float* __restrict__ att,
                           const float* __restrict__ b1, const float* __restrict__ g1,
                           const float* __restrict__ be1, const float* __restrict__ m1,
                           const float* __restrict__ v1, const float* __restrict__ Wc,
                           const float* __restrict__ bc, float* __restrict__ outp, int N) {
    int lane = threadIdx.x & 31;
    int n = (blockIdx.x * blockDim.x + threadIdx.x) >> 5;
    if (n >= N) return;
    float4 o0, o1;
    gat_core(n, lane, (const float4*)att, o0, o1);
    float t0 = o0.x + o1.x, t1 = o0.y + o1.y, t2 = o0.z + o1.z, t3 = o0.w + o1.w;
#pragma unroll
    for (int off = 8; off <= 16; off <<= 1) {
        t0 += __shfl_xor_sync(0xffffffffu, t0, off);
        t1 += __shfl_xor_sync(0xffffffffu, t1, off);
        t2 += __shfl_xor_sync(0xffffffffu, t2, off);
        t3 += __shfl_xor_sync(0xffffffffu, t3, off);
    }
    int cg = lane & 7;
    float4 bb = ((const float4*)b1)[cg];
    float4 gg = ((const float4*)g1)[cg];
    float4 be = ((const float4*)be1)[cg];
    float4 mm = ((const float4*)m1)[cg];
    float4 vv = ((const float4*)v1)[cg];
    float s0 = (t0 * 0.125f + bb.x - mm.x) * rsqrtf(vv.x + EPS_) * gg.x + be.x;
    float s1 = (t1 * 0.125f + bb.y - mm.y) * rsqrtf(vv.y + EPS_) * gg.y + be.y;
    float s2 = (t2 * 0.125f + bb.z - mm.z) * rsqrtf(vv.z + EPS_) * gg.z + be.z;
    float s3 = (t3 * 0.125f + bb.w - mm.w) * rsqrtf(vv.w + EPS_) * gg.w + be.w;
    int c0 = cg * 4;
    float y0 = s0 * Wc[(c0+0)*2] + s1 * Wc[(c0+1)*2] + s2 * Wc[(c0+2)*2] + s3 * Wc[(c0+3)*2];
    float y1 = s0 * Wc[(c0+0)*2+1] + s1 * Wc[(c0+1)*2+1] + s2 * Wc[(c0+2)*2+1] + s3 * Wc[(c0+3)*2+1];
#pragma unroll
    for (int off = 4; off; off >>= 1) {
        y0 += __shfl_xor_sync(0xffffffffu, y0, off);
        y1 += __shfl_xor_sync(0xffffffffu, y1, off);
    }
    if (lane == 0) {
        outp[(long long)n * 2 + 0] = y0 + bc[0];
        outp[(long long)n * 2 + 1] = y1 + bc[1];
    }
}

// ---------------------------------------------------------------------------
extern "C" void kernel_launch(void* const* d_in, const int* in_sizes, int n_in,
                              void* d_out, int out_size) {
    const float* x    = (const float*)d_in[0];
    const void*  ei   = d_in[1];
    const float* Wl0  = (const float*)d_in[2];
    const float* Wr0  = (const float*)d_in[3];
    const float* att0 = (const float*)d_in[4];
    const float* b0   = (const float*)d_in[5];
    const float* g0   = (const float*)d_in[6];
    const float* be0  = (const float*)d_in[7];
    const float* m0   = (const float*)d_in[8];
    const float* v0   = (const float*)d_in[9];
    const float* Wl1  = (const float*)d_in[10];
    const float* Wr1  = (const float*)d_in[11];
    const float* att1 = (const float*)d_in[12];
    const float* b1   = (const float*)d_in[13];
    const float* g1   = (const float*)d_in[14];
    const float* be1  = (const float*)d_in[15];
    const float* m1   = (const float*)d_in[16];
    const float* v1   = (const float*)d_in[17];
    const float* Wc   = (const float*)d_in[18];
    const float* bc   = (const float*)d_in[19];
    float* out = (float*)d_out;

    int IN = in_sizes[2] / HC_;       // 128
    int N  = in_sizes[0] / IN;        // 50000
    int E  = in_sizes[1] / 2;         // 800000
    int Etot = E + N;
    int nb = (N + SCAN_B - 1) / SCAN_B;

    void *p_xl, *p_xr, *p_cnt, *p_a2, *p_w2;
    cudaGetSymbolAddress(&p_xl,  g_xl);
    cudaGetSymbolAddress(&p_xr,  g_xr);
    cudaGetSymbolAddress(&p_cnt, g_cnt);
    cudaGetSymbolAddress(&p_a2,  g_a2);
    cudaGetSymbolAddress(&p_w2,  g_w2);
    __nv_bfloat16* a2 = (__nv_bfloat16*)p_a2;
    __nv_bfloat16* w2 = (__nv_bfloat16*)p_w2;
    const size_t WSZ = 256 * 512;

    // Side stream: CSR build + layer-1 weight splits (joined before gat_layer0)
    cudaStream_t s1;
    cudaStreamCreateWithFlags(&s1, cudaStreamNonBlocking);
    cudaEvent_t eFork, eJoin;
    cudaEventCreateWithFlags(&eFork, cudaEventDisableTiming);
    cudaEventCreateWithFlags(&eJoin, cudaEventDisableTiming);
    cudaEventRecord(eFork, 0);
    cudaStreamWaitEvent(s1, eFork, 0);

    k_detect<<<1, 1, 0, s1>>>((const int*)ei, E);
    cudaMemsetAsync(p_cnt, 0, (size_t)N * sizeof(int), s1);
    k_convert<<<(2 * E + 255) / 256, 256, 0, s1>>>(ei, E);
    k_scan_a<<<nb, SCAN_B, 0, s1>>>(N);
    k_scan_b<<<1, SCAN_B, 0, s1>>>(nb);
    k_scan_c<<<nb, SCAN_B, 0, s1>>>(N);
    k_scatter<<<(Etot + 255) / 256, 256, 0, s1>>>(E, N);
    k_split_w<<<(HC_ * HC_ + 255) / 256, 256, 0, s1>>>(Wl1, w2 + 2 * WSZ, HC_, HC_);
    k_split_w<<<(HC_ * HC_ + 255) / 256, 256, 0, s1>>>(Wr1, w2 + 3 * WSZ, HC_, HC_);
    cudaEventRecord(eJoin, s1);

    // Main stream: layer-0 prep splits
    k_split_w<<<(IN * HC_ + 255) / 256, 256>>>(Wl0, w2, IN, HC_);
    k_split_w<<<(IN * HC_ + 255) / 256, 256>>>(Wr0, w2 + WSZ, IN, HC_);
    k_split_x<<<(N * IN / 4 + 255) / 256, 256>>>(x, N * IN / 4);

    dim3 mgrid(HC_ / BN, (N + BM - 1) / BM, 2);
    int nodeBlocks = (N * 32 + 255) / 256;

    // ---------------- layer 0 (K2 = 2*IN = 256) ----------------
    hmma_gemm<<<mgrid, 256>>>(a2, w2, w2 + WSZ,
                              (float*)p_xl, (float*)p_xr, N, 2 * IN, HC_);
    cudaStreamWaitEvent(0, eJoin, 0);
    gat_layer0<<<nodeBlocks, 256>>>(att0, b0, g0, be0, m0, v0, N);

    // ---------------- layer 1 (K2 = 2*HC = 512) ----------------
    hmma_gemm<<<mgrid, 256>>>(a2, w2 + 2 * WSZ, w2 + 3 * WSZ,
                              (float*)p_xl, (float*)p_xr, N, 2 * HC_, HC_);
    gat_layer1<<<nodeBlocks, 256>>>(att1, b1, g1, be1, m1, v1, Wc, bc, out, N);
}

// round 14
// speedup vs baseline: 3.1120x; 1.0558x over previous
#include <cuda_runtime.h>
#include <cuda_bf16.h>
#include <cstdint>

// ---------------------------------------------------------------------------
// GATv2 (2 layers) + BN + ELU + linear classifier.
// N=50000, E=800000, IN=128, H=8, C=32, NC=2.
// GEMMs: TF32 mma.sync.m16n8k8 (sm_80 PTX), cp.async double-buffered,
// rna-prerounded operands (well-defined TF32, ~8x more accurate than bf16).
// CSR build overlapped; warp-per-node online-softmax fused attention.
// ---------------------------------------------------------------------------

#define NMAX 50000
#define EMAX 800000
#define H_ 8
#define C_ 32
#define HC_ 256       // H*C
#define ETOTMAX (EMAX + NMAX)
#define EPS_ 1e-5f
#define SLOPE_ 0.2f
#define SCAN_B 256
#define NBLK ((NMAX + SCAN_B - 1) / SCAN_B)

// ------------------------- static device scratch ---------------------------
__device__ float g_xl[(size_t)NMAX * HC_];
__device__ float g_xr[(size_t)NMAX * HC_];
// A operand (tf32-rounded fp32). Layer 0: rounded x, pitch 128.
// Layer 1: rounded h, pitch 256.
__device__ __align__(16) float g_af[(size_t)NMAX * HC_];
// Transposed tf32-rounded weights: slots 0/1 layer-0 [256][128],
// slots 2/3 layer-1 [256][256].
__device__ __align__(16) float g_wt[4][256 * 256];
__device__ int   g_src[EMAX];
__device__ int   g_dst[EMAX];
__device__ int   g_off[NMAX + 1];
__device__ int   g_cnt[NMAX];
__device__ int   g_blk[NBLK];
__device__ int   g_esrc[ETOTMAX];
__device__ int   g_is64;

// ------------------------- PTX helpers --------------------------------------
__device__ __forceinline__ uint32_t smem_to_u32(const void* p) {
    uint32_t a;
    asm("{ .reg .u64 t; cvta.to.shared.u64 t, %1; cvt.u32.u64 %0, t; }"
        : "=r"(a) : "l"(p));
    return a;
}
__device__ __forceinline__ float tf32r(float f) {
    uint32_t u;
    asm("cvt.rna.tf32.f32 %0, %1;" : "=r"(u) : "f"(f));
    return __uint_as_float(u);
}
__device__ __forceinline__ void cp16(uint32_t dst, const void* src) {
    asm volatile("cp.async.cg.shared.global [%0], [%1], 16;"
                 :: "r"(dst), "l"(src) : "memory");
}
__device__ __forceinline__ void mma_tf32(float* c, const uint32_t* a, const uint32_t* b) {
    asm volatile("mma.sync.aligned.m16n8k8.row.col.f32.tf32.tf32.f32 "
                 "{%0,%1,%2,%3}, {%4,%5,%6,%7}, {%8,%9}, {%0,%1,%2,%3};"
                 : "+f"(c[0]), "+f"(c[1]), "+f"(c[2]), "+f"(c[3])
                 : "r"(a[0]), "r"(a[1]), "r"(a[2]), "r"(a[3]),
                   "r"(b[0]), "r"(b[1]));
}

// ------------------------- edge index conversion + histogram ----------------
__global__ void k_detect(const int* __restrict__ ei, int E) {
    int ok64 = 1;
    int limit = (E > 64) ? 64 : E;
    for (int i = 0; i < limit; i++)
        if (ei[2 * i + 1] != 0) { ok64 = 0; break; }
    g_is64 = ok64;
}

__global__ void k_convert(const void* __restrict__ ei, int E) {
    int i = blockIdx.x * blockDim.x + threadIdx.x;
    int tot = 2 * E;
    if (i >= tot) return;
    int v;
    if (g_is64) v = (int)((const long long*)ei)[i];
    else        v = ((const int*)ei)[i];
    if (i < E) g_src[i] = v;
    else {
        g_dst[i - E] = v;
        atomicAdd(&g_cnt[v], 1);
    }
}

// ------------------------- 3-phase multi-block scan -------------------------
__device__ __forceinline__ int block_incl_scan(int* sh, int t, int v) {
    sh[t] = v;
    __syncthreads();
#pragma unroll
    for (int off = 1; off < SCAN_B; off <<= 1) {
        int u = (t >= off) ? sh[t - off] : 0;
        __syncthreads();
        sh[t] += u;
        __syncthreads();
    }
    return sh[t];
}

__global__ void k_scan_a(int N) {
    __shared__ int sh[SCAN_B];
    int t = threadIdx.x;
    int i = blockIdx.x * SCAN_B + t;
    int c = (i < N) ? (g_cnt[i] + 1) : 0;
    int incl = block_incl_scan(sh, t, c);
    if (i < N) {
        g_off[i + 1] = incl;
        g_cnt[i] = incl - c;
    }
    if (t == SCAN_B - 1) g_blk[blockIdx.x] = incl;
}

__global__ void k_scan_b(int nb) {
    __shared__ int sh[SCAN_B];
    int t = threadIdx.x;
    int v = (t < nb) ? g_blk[t] : 0;
    int incl = block_incl_scan(sh, t, v);
    if (t < nb) g_blk[t] = incl - v;
}

__global__ void k_scan_c(int N) {
    int i = blockIdx.x * SCAN_B + threadIdx.x;
    int add = g_blk[blockIdx.x];
    if (i < N) {
        g_off[i + 1] += add;
        g_cnt[i] += add;
    }
    if (i == 0) g_off[0] = 0;
}

__global__ void k_scatter(int E, int N) {
    int i = blockIdx.x * blockDim.x + threadIdx.x;
    if (i < E) {
        int pos = atomicAdd(&g_cnt[g_dst[i]], 1);
        g_esrc[pos] = g_src[i];
    } else if (i < E + N) {
        int n = i - E;
        int pos = atomicAdd(&g_cnt[n], 1);
        g_esrc[pos] = n;
    }
}

// ------------------------- tf32 prep ----------------------------------------
// x [N*128] fp32 -> g_af (rna-rounded), float4 granularity
__global__ void k_round_x(const float* __restrict__ x, int total4) {
    int i = blockIdx.x * blockDim.x + threadIdx.x;
    if (i >= total4) return;
    float4 v = ((const float4*)x)[i];
    ((float4*)g_af)[i] = make_float4(tf32r(v.x), tf32r(v.y), tf32r(v.z), tf32r(v.w));
}

// W [K, Nn] fp32 -> o [Nn, K] fp32 (transposed, rna-rounded)
__global__ void k_trans_w(const float* __restrict__ W, float* __restrict__ o,
                          int K, int Nn) {
    int i = blockIdx.x * blockDim.x + threadIdx.x;
    if (i >= K * Nn) return;
    int k = i / Nn, n = i % Nn;
    o[(size_t)n * K + k] = tf32r(W[i]);
}

// ------------------------- TF32 HMMA GEMM pair ------------------------------
// C[z][M,Nn] = A[M,K] @ Wt[z][Nn,K]^T  (tf32 in, fp32 accum).
// 128x128 CTA tile, 8 warps (4m x 2n), warp tile 32x64, BK=16,
// cp.async double-buffered stages.
#define BM 128
#define BN 128
#define BK 16
#define LDT 20    // floats; 20*8 % 32 == 0 -> conflict-free fragment LDS

__global__ void __launch_bounds__(256, 2)
tf32_gemm(const float* __restrict__ A,
          const float* __restrict__ B0t, const float* __restrict__ B1t,
          float* __restrict__ C0, float* __restrict__ C1,
          int M, int K, int Nn) {
    const float* Bt = (blockIdx.z == 0) ? B0t : B1t;
    float* Cc = (blockIdx.z == 0) ? C0 : C1;
    __shared__ __align__(16) float As[2][BM][LDT];
    __shared__ __align__(16) float Bs[2][BN][LDT];
    int tid = threadIdx.x;
    int lane = tid & 31, warp = tid >> 5;
    int wm = warp & 3, wn = warp >> 2;
    int rowBase = blockIdx.y * BM;
    int colBase = blockIdx.x * BN;

    float c[2][8][4] = {};

    int ldRow = tid >> 2;            // 0..63
    int ldQ = (tid & 3) * 4;         // 0,4,8,12
    uint32_t sA0 = smem_to_u32(&As[0][0][0]);
    uint32_t sB0 = smem_to_u32(&Bs[0][0][0]);

    int nch = K / BK;
    // ---- stage macro (cp.async 16B) ----
#define STAGE(buf, k0) do {                                                      \
    int r0 = ldRow, r1 = ldRow + 64;                                             \
    int ga0 = min(rowBase + r0, M - 1);                                          \
    int ga1 = min(rowBase + r1, M - 1);                                          \
    cp16(sA0 + (((buf) * BM + r0) * LDT + ldQ) * 4, A + (size_t)ga0 * K + (k0) + ldQ); \
    cp16(sA0 + (((buf) * BM + r1) * LDT + ldQ) * 4, A + (size_t)ga1 * K + (k0) + ldQ); \
    cp16(sB0 + (((buf) * BN + r0) * LDT + ldQ) * 4, Bt + (size_t)(colBase + r0) * K + (k0) + ldQ); \
    cp16(sB0 + (((buf) * BN + r1) * LDT + ldQ) * 4, Bt + (size_t)(colBase + r1) * K + (k0) + ldQ); \
    asm volatile("cp.async.commit_group;" ::: "memory");                         \
} while (0)

    STAGE(0, 0);
    for (int c0 = 0; c0 < nch; c0++) {
        int buf = c0 & 1;
        if (c0 + 1 < nch) {
            STAGE(buf ^ 1, (c0 + 1) * BK);
            asm volatile("cp.async.wait_group 1;" ::: "memory");
        } else {
            asm volatile("cp.async.wait_group 0;" ::: "memory");
        }
        __syncthreads();
#pragma unroll
        for (int kk = 0; kk < BK; kk += 8) {
            int ac = kk + (lane & 3);
            uint32_t a[2][4];
#pragma unroll
            for (int mi = 0; mi < 2; mi++) {
                int ar = wm * 32 + mi * 16 + (lane >> 2);
                a[mi][0] = __float_as_uint(As[buf][ar][ac]);
                a[mi][1] = __float_as_uint(As[buf][ar + 8][ac]);
                a[mi][2] = __float_as_uint(As[buf][ar][ac + 4]);
                a[mi][3] = __float_as_uint(As[buf][ar + 8][ac + 4]);
            }
#pragma unroll
            for (int ni = 0; ni < 8; ni++) {
                int br = wn * 64 + ni * 8 + (lane >> 2);
                uint32_t b[2];
                b[0] = __float_as_uint(Bs[buf][br][ac]);
                b[1] = __float_as_uint(Bs[buf][br][ac + 4]);
#pragma unroll
                for (int mi = 0; mi < 2; mi++)
                    mma_tf32(c[mi][ni], a[mi], b);
            }
        }
        __syncthreads();
    }
#undef STAGE

    // epilogue: m16n8 C fragment: c0,c1 at (row, col), (row, col+1);
    // c2,c3 at (row+8, ...)
    int r0 = rowBase + wm * 32 + (lane >> 2);
    int cg0 = colBase + wn * 64 + (lane & 3) * 2;
#pragma unroll
    for (int mi = 0; mi < 2; mi++) {
#pragma unroll
        for (int ni = 0; ni < 8; ni++) {
            int row = r0 + mi * 16;
            int col = cg0 + ni * 8;
            if (row < M)
                *(float2*)(Cc + (size_t)row * Nn + col) =
                    make_float2(c[mi][ni][0], c[mi][ni][1]);
            if (row + 8 < M)
                *(float2*)(Cc + (size_t)(row + 8) * Nn + col) =
                    make_float2(c[mi][ni][2], c[mi][ni][3]);
        }
    }
}

// ------------------------- fused per-node attention (online softmax) --------
__device__ __forceinline__ void gat_core(int n, int lane, const float4* att4,
                                         float4& o0, float4& o1) {
    int beg = g_off[n], end = g_off[n + 1];
    const float4* xr4 = (const float4*)(g_xr + (long long)n * HC_);
    float4 r0 = xr4[lane], r1 = xr4[lane + 32];
    float4 a0 = att4[lane], a1 = att4[lane + 32];
    float mx0 = -3.4e38f, mx1 = -3.4e38f;
    float den0 = 0.f, den1 = 0.f;
    float4 ac0 = make_float4(0.f, 0.f, 0.f, 0.f);
    float4 ac1 = make_float4(0.f, 0.f, 0.f, 0.f);
    for (int i = beg; i < end; i++) {
        int s = g_esrc[i];
        const float4* xl4 = (const float4*)(g_xl + (long long)s * HC_);
        float4 l0 = xl4[lane], l1 = xl4[lane + 32];
        float v, s0 = 0.f, s1 = 0.f;
        v = l0.x + r0.x; v = (v > 0.f) ? v : SLOPE_ * v; s0 += v * a0.x;
        v = l0.y + r0.y; v = (v > 0.f) ? v : SLOPE_ * v; s0 += v * a0.y;
        v = l0.z + r0.z; v = (v > 0.f) ? v : SLOPE_ * v; s0 += v * a0.z;
        v = l0.w + r0.w; v = (v > 0.f) ? v : SLOPE_ * v; s0 += v * a0.w;
        v = l1.x + r1.x; v = (v > 0.f) ? v : SLOPE_ * v; s1 += v * a1.x;
        v = l1.y + r1.y; v = (v > 0.f) ? v : SLOPE_ * v; s1 += v * a1.y;
        v = l1.z + r1.z; v = (v > 0.f) ? v : SLOPE_ * v; s1 += v * a1.z;
        v = l1.w + r1.w; v = (v > 0.f) ? v : SLOPE_ * v; s1 += v * a1.w;
#pragma unroll
        for (int off = 4; off; off >>= 1) {
            s0 += __shfl_xor_sync(0xffffffffu, s0, off);
            s1 += __shfl_xor_sync(0xffffffffu, s1, off);
        }
        float nm0 = fmaxf(mx0, s0);
        float c0 = __expf(mx0 - nm0);
        float w0 = __expf(s0 - nm0);
        mx0 = nm0;
        den0 = den0 * c0 + w0;
        ac0.x = ac0.x * c0 + w0 * l0.x;
        ac0.y = ac0.y * c0 + w0 * l0.y;
        ac0.z = ac0.z * c0 + w0 * l0.z;
        ac0.w = ac0.w * c0 + w0 * l0.w;
        float nm1 = fmaxf(mx1, s1);
        float c1 = __expf(mx1 - nm1);
        float w1 = __expf(s1 - nm1);
        mx1 = nm1;
        den1 = den1 * c1 + w1;
        ac1.x = ac1.x * c1 + w1 * l1.x;
        ac1.y = ac1.y * c1 + w1 * l1.y;
        ac1.z = ac1.z * c1 + w1 * l1.z;
        ac1.w = ac1.w * c1 + w1 * l1.w;
    }
    float i0 = 1.f / den0, i1 = 1.f / den1;
    o0 = make_float4(ac0.x * i0, ac0.y * i0, ac0.z * i0, ac0.w * i0);
    o1 = make_float4(ac1.x * i1, ac1.y * i1, ac1.z * i1, ac1.w * i1);
}

// layer 0: h = elu(bn(out + b0)) -> tf32-rounded fp32 into g_af [N, 256]
__global__ void gat_layer0(const float* __restrict__ att,
                           const float* __restrict__ b0, const float* __restrict__ g0,
                           const float* __restrict__ be0, const float* __restrict__ m0,
                           const float* __restrict__ v0, int N) {
    int lane = threadIdx.x & 31;
    int n = (blockIdx.x * blockDim.x + threadIdx.x) >> 5;
    if (n >= N) return;
    float4 o0, o1;
    gat_core(n, lane, (const float4*)att, o0, o1);
    float out[8] = {o0.x, o0.y, o0.z, o0.w, o1.x, o1.y, o1.z, o1.w};
    float4* ph = (float4*)(g_af + (size_t)n * HC_);
#pragma unroll
    for (int half = 0; half < 2; half++) {
        int q = lane + half * 32;
        float4 bb = ((const float4*)b0)[q];
        float4 gg = ((const float4*)g0)[q];
        float4 be = ((const float4*)be0)[q];
        float4 mm = ((const float4*)m0)[q];
        float4 vv = ((const float4*)v0)[q];
        float xb[4] = {out[half*4+0] + bb.x, out[half*4+1] + bb.y,
                       out[half*4+2] + bb.z, out[half*4+3] + bb.w};
        float mu[4] = {mm.x, mm.y, mm.z, mm.w};
        float va[4] = {vv.x, vv.y, vv.z, vv.w};
        float ga[4] = {gg.x, gg.y, gg.z, gg.w};
        float ba[4] = {be.x, be.y, be.z, be.w};
        float r[4];
#pragma unroll
        for (int j = 0; j < 4; j++) {
            float xv = (xb[j] - mu[j]) * rsqrtf(va[j] + EPS_) * ga[j] + ba[j];
            float rr = (xv > 0.f) ? xv : (__expf(xv) - 1.f);
            r[j] = tf32r(rr);
        }
        ph[q] = make_float4(r[0], r[1], r[2], r[3]);
    }
}

// layer 1: s = bn(mean_h(out) + b1); y = s @ Wc + bc  -> out [N, 2]
__global__ void gat_layer1(const float* __restrict__ att,
                           const float* __restrict__ b1, const float* __restrict__ g1,
                           const float* __restrict__ be1, const float* __restrict__ m1,
                           const float* __restrict__ v1, const float* __restrict__ Wc,
                           const float* __restrict__ bc, float* __restrict__ outp, int N) {
    int lane = threadIdx.x & 31;
    int n = (blockIdx.x * blockDim.x + threadIdx.x) >> 5;
    if (n >= N) return;
    float4 o0, o1;
    gat_core(n, lane, (const float4*)att, o0, o1);
    float t0 = o0.x + o1.x, t1 = o0.y + o1.y, t2 = o0.z + o1.z, t3 = o0.w + o1.w;
#pragma unroll
    for (int off = 8; off <= 16; off <<= 1) {
        t0 += __shfl_xor_sync(0xffffffffu, t0, off);
        t1 += __shfl_xor_sync(0xffffffffu, t1, off);
        t2 += __shfl_xor_sync(0xffffffffu, t2, off);
        t3 += __shfl_xor_sync(0xffffffffu, t3, off);
    }
    int cg = lane & 7;
    float4 bb = ((const float4*)b1)[cg];
    float4 gg = ((const float4*)g1)[cg];
    float4 be = ((const float4*)be1)[cg];
    float4 mm = ((const float4*)m1)[cg];
    float4 vv = ((const float4*)v1)[cg];
    float s0 = (t0 * 0.125f + bb.x - mm.x) * rsqrtf(vv.x + EPS_) * gg.x + be.x;
    float s1 = (t1 * 0.125f + bb.y - mm.y) * rsqrtf(vv.y + EPS_) * gg.y + be.y;
    float s2 = (t2 * 0.125f + bb.z - mm.z) * rsqrtf(vv.z + EPS_) * gg.z + be.z;
    float s3 = (t3 * 0.125f + bb.w - mm.w) * rsqrtf(vv.w + EPS_) * gg.w + be.w;
    int c0 = cg * 4;
    float y0 = s0 * Wc[(c0+0)*2] + s1 * Wc[(c0+1)*2] + s2 * Wc[(c0+2)*2] + s3 * Wc[(c0+3)*2];
    float y1 = s0 * Wc[(c0+0)*2+1] + s1 * Wc[(c0+1)*2+1] + s2 * Wc[(c0+2)*2+1] + s3 * Wc[(c0+3)*2+1];
#pragma unroll
    for (int off = 4; off; off >>= 1) {
        y0 += __shfl_xor_sync(0xffffffffu, y0, off);
        y1 += __shfl_xor_sync(0xffffffffu, y1, off);
    }
    if (lane == 0) {
        outp[(long long)n * 2 + 0] = y0 + bc[0];
        outp[(long long)n * 2 + 1] = y1 + bc[1];
    }
}

// ---------------------------------------------------------------------------
extern "C" void kernel_launch(void* const* d_in, const int* in_sizes, int n_in,
                              void* d_out, int out_size) {
    const float* x    = (const float*)d_in[0];
    const void*  ei   = d_in[1];
    const float* Wl0  = (const float*)d_in[2];
    const float* Wr0  = (const float*)d_in[3];
    const float* att0 = (const float*)d_in[4];
    const float* b0   = (const float*)d_in[5];
    const float* g0   = (const float*)d_in[6];
    const float* be0  = (const float*)d_in[7];
    const float* m0   = (const float*)d_in[8];
    const float* v0   = (const float*)d_in[9];
    const float* Wl1  = (const float*)d_in[10];
    const float* Wr1  = (const float*)d_in[11];
    const float* att1 = (const float*)d_in[12];
    const float* b1   = (const float*)d_in[13];
    const float* g1   = (const float*)d_in[14];
    const float* be1  = (const float*)d_in[15];
    const float* m1   = (const float*)d_in[16];
    const float* v1   = (const float*)d_in[17];
    const float* Wc   = (const float*)d_in[18];
    const float* bc   = (const float*)d_in[19];
    float* out = (float*)d_out;

    int IN = in_sizes[2] / HC_;       // 128
    int N  = in_sizes[0] / IN;        // 50000
    int E  = in_sizes[1] / 2;         // 800000
    int Etot = E + N;
    int nb = (N + SCAN_B - 1) / SCAN_B;

    void *p_xl, *p_xr, *p_cnt, *p_af, *p_wt;
    cudaGetSymbolAddress(&p_xl,  g_xl);
    cudaGetSymbolAddress(&p_xr,  g_xr);
    cudaGetSymbolAddress(&p_cnt, g_cnt);
    cudaGetSymbolAddress(&p_af,  g_af);
    cudaGetSymbolAddress(&p_wt,  g_wt);
    float* af = (float*)p_af;
    float* wt = (float*)p_wt;
    const size_t WSZ = 256 * 256;

    // Side stream: CSR build + layer-1 weight transposes
    cudaStream_t s1;
    cudaStreamCreateWithFlags(&s1, cudaStreamNonBlocking);
    cudaEvent_t eFork, eJoin;
    cudaEventCreateWithFlags(&eFork, cudaEventDisableTiming);
    cudaEventCreateWithFlags(&eJoin, cudaEventDisableTiming);
    cudaEventRecord(eFork, 0);
    cudaStreamWaitEvent(s1, eFork, 0);

    k_detect<<<1, 1, 0, s1>>>((const int*)ei, E);
    cudaMemsetAsync(p_cnt, 0, (size_t)N * sizeof(int), s1);
    k_convert<<<(2 * E + 255) / 256, 256, 0, s1>>>(ei, E);
    k_scan_a<<<nb, SCAN_B, 0, s1>>>(N);
    k_scan_b<<<1, SCAN_B, 0, s1>>>(nb);
    k_scan_c<<<nb, SCAN_B, 0, s1>>>(N);
    k_scatter<<<(Etot + 255) / 256, 256, 0, s1>>>(E, N);
    k_trans_w<<<(HC_ * HC_ + 255) / 256, 256, 0, s1>>>(Wl1, wt + 2 * WSZ, HC_, HC_);
    k_trans_w<<<(HC_ * HC_ + 255) / 256, 256, 0, s1>>>(Wr1, wt + 3 * WSZ, HC_, HC_);
    cudaEventRecord(eJoin, s1);

    // Main stream: layer-0 prep (transpose weights + round x)
    k_trans_w<<<(IN * HC_ + 255) / 256, 256>>>(Wl0, wt, IN, HC_);
    k_trans_w<<<(IN * HC_ + 255) / 256, 256>>>(Wr0, wt + WSZ, IN, HC_);
    k_round_x<<<(N * IN / 4 + 255) / 256, 256>>>(x, N * IN / 4);

    dim3 mgrid(HC_ / BN, (N + BM - 1) / BM, 2);
    int nodeBlocks = (N * 32 + 255) / 256;

    // ---------------- layer 0 (K = IN = 128) ----------------
    tf32_gemm<<<mgrid, 256>>>(af, wt, wt + WSZ,
                              (float*)p_xl, (float*)p_xr, N, IN, HC_);
    cudaStreamWaitEvent(0, eJoin, 0);
    gat_layer0<<<nodeBlocks, 256>>>(att0, b0, g0, be0, m0, v0, N);

    // ---------------- layer 1 (K = HC = 256) ----------------
    tf32_gemm<<<mgrid, 256>>>(af, wt + 2 * WSZ, wt + 3 * WSZ,
                              (float*)p_xl, (float*)p_xr, N, HC_, HC_);
    gat_layer1<<<nodeBlocks, 256>>>(att1, b1, g1, be1, m1, v1, Wc, bc, out, N);
}

// round 17
// speedup vs baseline: 3.2912x; 1.0576x over previous
#include <cuda_runtime.h>
#include <cuda_bf16.h>
#include <cstdint>

// ---------------------------------------------------------------------------
// GATv2 (2 layers) + BN + ELU + linear classifier.
// N=50000, E=800000, IN=128, H=8, C=32, NC=2.
// GEMMs: TF32 mma.sync.m16n8k8, cp.async double-buffered, in-kernel rna
// rounding of A (x consumed directly, no rounding pass).
// CSR build overlapped on ONE side stream (graph topology identical to the
// passing round-13 run — avoids the 2MB teardown-leak from multi-stream
// graphs). Warp-per-node online-softmax attention with next-edge prefetch.
// ---------------------------------------------------------------------------

#define NMAX 50000
#define EMAX 800000
#define H_ 8
#define C_ 32
#define HC_ 256       // H*C
#define ETOTMAX (EMAX + NMAX)
#define EPS_ 1e-5f
#define SLOPE_ 0.2f
#define SCAN_B 256
#define NBLK ((NMAX + SCAN_B - 1) / SCAN_B)

// ------------------------- static device scratch ---------------------------
__device__ float g_xl[(size_t)NMAX * HC_];
__device__ float g_xr[(size_t)NMAX * HC_];
// h (tf32-prerounded fp32), pitch 256 — layer-1 A operand
__device__ __align__(16) float g_af[(size_t)NMAX * HC_];
// Transposed tf32-rounded weights: slots 0/1 layer-0 [256][128],
// slots 2/3 layer-1 [256][256].
__device__ __align__(16) float g_wt[4][256 * 256];
__device__ int   g_src[EMAX];
__device__ int   g_dst[EMAX];
__device__ int   g_off[NMAX + 1];
__device__ int   g_cnt[NMAX];
__device__ int   g_blk[NBLK];
__device__ int   g_esrc[ETOTMAX];
__device__ int   g_is64;

// ------------------------- PTX helpers --------------------------------------
__device__ __forceinline__ uint32_t smem_to_u32(const void* p) {
    uint32_t a;
    asm("{ .reg .u64 t; cvta.to.shared.u64 t, %1; cvt.u32.u64 %0, t; }"
        : "=r"(a) : "l"(p));
    return a;
}
__device__ __forceinline__ float tf32r(float f) {
    uint32_t u;
    asm("cvt.rna.tf32.f32 %0, %1;" : "=r"(u) : "f"(f));
    return __uint_as_float(u);
}
__device__ __forceinline__ uint32_t tf32u(float f) {
    uint32_t u;
    asm("cvt.rna.tf32.f32 %0, %1;" : "=r"(u) : "f"(f));
    return u;
}
__device__ __forceinline__ void cp16(uint32_t dst, const void* src) {
    asm volatile("cp.async.cg.shared.global [%0], [%1], 16;"
                 :: "r"(dst), "l"(src) : "memory");
}
__device__ __forceinline__ void mma_tf32(float* c, const uint32_t* a, const uint32_t* b) {
    asm volatile("mma.sync.aligned.m16n8k8.row.col.f32.tf32.tf32.f32 "
                 "{%0,%1,%2,%3}, {%4,%5,%6,%7}, {%8,%9}, {%0,%1,%2,%3};"
                 : "+f"(c[0]), "+f"(c[1]), "+f"(c[2]), "+f"(c[3])
                 : "r"(a[0]), "r"(a[1]), "r"(a[2]), "r"(a[3]),
                   "r"(b[0]), "r"(b[1]));
}

// ------------------------- edge index conversion + histogram ----------------
__global__ void k_detect(const int* __restrict__ ei, int E) {
    int ok64 = 1;
    int limit = (E > 64) ? 64 : E;
    for (int i = 0; i < limit; i++)
        if (ei[2 * i + 1] != 0) { ok64 = 0; break; }
    g_is64 = ok64;
}

__global__ void k_convert(const void* __restrict__ ei, int E) {
    int i = blockIdx.x * blockDim.x + threadIdx.x;
    int tot = 2 * E;
    if (i >= tot) return;
    int v;
    if (g_is64) v = (int)((const long long*)ei)[i];
    else        v = ((const int*)ei)[i];
    if (i < E) g_src[i] = v;
    else {
        g_dst[i - E] = v;
        atomicAdd(&g_cnt[v], 1);
    }
}

// ------------------------- 3-phase multi-block scan -------------------------
__device__ __forceinline__ int block_incl_scan(int* sh, int t, int v) {
    sh[t] = v;
    __syncthreads();
#pragma unroll
    for (int off = 1; off < SCAN_B; off <<= 1) {
        int u = (t >= off) ? sh[t - off] : 0;
        __syncthreads();
        sh[t] += u;
        __syncthreads();
    }
    return sh[t];
}

__global__ void k_scan_a(int N) {
    __shared__ int sh[SCAN_B];
    int t = threadIdx.x;
    int i = blockIdx.x * SCAN_B + t;
    int c = (i < N) ? (g_cnt[i] + 1) : 0;
    int incl = block_incl_scan(sh, t, c);
    if (i < N) {
        g_off[i + 1] = incl;
        g_cnt[i] = incl - c;
    }
    if (t == SCAN_B - 1) g_blk[blockIdx.x] = incl;
}

__global__ void k_scan_b(int nb) {
    __shared__ int sh[SCAN_B];
    int t = threadIdx.x;
    int v = (t < nb) ? g_blk[t] : 0;
    int incl = block_incl_scan(sh, t, v);
    if (t < nb) g_blk[t] = incl - v;
}

__global__ void k_scan_c(int N) {
    int i = blockIdx.x * SCAN_B + threadIdx.x;
    int add = g_blk[blockIdx.x];
    if (i < N) {
        g_off[i + 1] += add;
        g_cnt[i] += add;
    }
    if (i == 0) g_off[0] = 0;
}

__global__ void k_scatter(int E, int N) {
    int i = blockIdx.x * blockDim.x + threadIdx.x;
    if (i < E) {
        int pos = atomicAdd(&g_cnt[g_dst[i]], 1);
        g_esrc[pos] = g_src[i];
    } else if (i < E + N) {
        int n = i - E;
        int pos = atomicAdd(&g_cnt[n], 1);
        g_esrc[pos] = n;
    }
}

// ------------------------- tf32 prep ----------------------------------------
// W [K, Nn] fp32 -> o [Nn, K] fp32 (transposed, rna-rounded)
__global__ void k_trans_w(const float* __restrict__ W, float* __restrict__ o,
                          int K, int Nn) {
    int i = blockIdx.x * blockDim.x + threadIdx.x;
    if (i >= K * Nn) return;
    int k = i / Nn, n = i % Nn;
    o[(size_t)n * K + k] = tf32r(W[i]);
}

// ------------------------- TF32 HMMA GEMM pair ------------------------------
// C[z][M,Nn] = A[M,K] @ Wt[z][Nn,K]^T  (A rounded in-kernel; Wt prerounded).
// 128x128 CTA tile, 8 warps (4m x 2n), warp tile 32x64, BK=16,
// cp.async double-buffered.
#define BM 128
#define BN 128
#define BK 16
#define LDT 20    // floats; 20*8 % 32 == 0 -> conflict-free fragment LDS

__global__ void __launch_bounds__(256, 2)
tf32_gemm(const float* __restrict__ A,
          const float* __restrict__ B0t, const float* __restrict__ B1t,
          float* __restrict__ C0, float* __restrict__ C1,
          int M, int K, int Nn) {
    const float* Bt = (blockIdx.z == 0) ? B0t : B1t;
    float* Cc = (blockIdx.z == 0) ? C0 : C1;
    __shared__ __align__(16) float As[2][BM][LDT];
    __shared__ __align__(16) float Bs[2][BN][LDT];
    int tid = threadIdx.x;
    int lane = tid & 31, warp = tid >> 5;
    int wm = warp & 3, wn = warp >> 2;
    int rowBase = blockIdx.y * BM;
    int colBase = blockIdx.x * BN;

    float c[2][8][4] = {};

    int ldRow = tid >> 2;            // 0..63
    int ldQ = (tid & 3) * 4;         // 0,4,8,12
    uint32_t sA0 = smem_to_u32(&As[0][0][0]);
    uint32_t sB0 = smem_to_u32(&Bs[0][0][0]);

    int nch = K / BK;
#define STAGE(buf, k0) do {                                                      \
    int r0 = ldRow, r1 = ldRow + 64;                                             \
    int ga0 = min(rowBase + r0, M - 1);                                          \
    int ga1 = min(rowBase + r1, M - 1);                                          \
    cp16(sA0 + (((buf) * BM + r0) * LDT + ldQ) * 4, A + (size_t)ga0 * K + (k0) + ldQ); \
    cp16(sA0 + (((buf) * BM + r1) * LDT + ldQ) * 4, A + (size_t)ga1 * K + (k0) + ldQ); \
    cp16(sB0 + (((buf) * BN + r0) * LDT + ldQ) * 4, Bt + (size_t)(colBase + r0) * K + (k0) + ldQ); \
    cp16(sB0 + (((buf) * BN + r1) * LDT + ldQ) * 4, Bt + (size_t)(colBase + r1) * K + (k0) + ldQ); \
    asm volatile("cp.async.commit_group;" ::: "memory");                         \
} while (0)

    STAGE(0, 0);
    for (int c0 = 0; c0 < nch; c0++) {
        int buf = c0 & 1;
        if (c0 + 1 < nch) {
            STAGE(buf ^ 1, (c0 + 1) * BK);
            asm volatile("cp.async.wait_group 1;" ::: "memory");
        } else {
            asm volatile("cp.async.wait_group 0;" ::: "memory");
        }
        __syncthreads();
#pragma unroll
        for (int kk = 0; kk < BK; kk += 8) {
            int ac = kk + (lane & 3);
            uint32_t a[2][4];
#pragma unroll
            for (int mi = 0; mi < 2; mi++) {
                int ar = wm * 32 + mi * 16 + (lane >> 2);
                a[mi][0] = tf32u(As[buf][ar][ac]);
                a[mi][1] = tf32u(As[buf][ar + 8][ac]);
                a[mi][2] = tf32u(As[buf][ar][ac + 4]);
                a[mi][3] = tf32u(As[buf][ar + 8][ac + 4]);
            }
#pragma unroll
            for (int ni = 0; ni < 8; ni++) {
                int br = wn * 64 + ni * 8 + (lane >> 2);
                uint32_t b[2];
                b[0] = __float_as_uint(Bs[buf][br][ac]);
                b[1] = __float_as_uint(Bs[buf][br][ac + 4]);
#pragma unroll
                for (int mi = 0; mi < 2; mi++)
                    mma_tf32(c[mi][ni], a[mi], b);
            }
        }
        __syncthreads();
    }
#undef STAGE

    int r0 = rowBase + wm * 32 + (lane >> 2);
    int cg0 = colBase + wn * 64 + (lane & 3) * 2;
#pragma unroll
    for (int mi = 0; mi < 2; mi++) {
#pragma unroll
        for (int ni = 0; ni < 8; ni++) {
            int row = r0 + mi * 16;
            int col = cg0 + ni * 8;
            if (row < M)
                *(float2*)(Cc + (size_t)row * Nn + col) =
                    make_float2(c[mi][ni][0], c[mi][ni][1]);
            if (row + 8 < M)
                *(float2*)(Cc + (size_t)(row + 8) * Nn + col) =
                    make_float2(c[mi][ni][2], c[mi][ni][3]);
        }
    }
}

// ------------------------- fused per-node attention (online softmax) --------
// Single pass over CSR edges with next-edge prefetch (2x MLP vs serial).
__device__ __forceinline__ void gat_core(int n, int lane, const float4* att4,
                                         float4& o0, float4& o1) {
    int beg = g_off[n], end = g_off[n + 1];
    const float4* xr4 = (const float4*)(g_xr + (long long)n * HC_);
    float4 r0 = xr4[lane], r1 = xr4[lane + 32];
    float4 a0 = att4[lane], a1 = att4[lane + 32];
    float mx0 = -3.4e38f, mx1 = -3.4e38f;
    float den0 = 0.f, den1 = 0.f;
    float4 ac0 = make_float4(0.f, 0.f, 0.f, 0.f);
    float4 ac1 = make_float4(0.f, 0.f, 0.f, 0.f);
    // prefetch first edge (beg < end always: self loop)
    int s = g_esrc[beg];
    const float4* p = (const float4*)(g_xl + (long long)s * HC_);
    float4 l0 = p[lane], l1 = p[lane + 32];
    for (int i = beg; i < end; i++) {
        float4 cl0 = l0, cl1 = l1;
        if (i + 1 < end) {
            int sn = g_esrc[i + 1];
            const float4* pn = (const float4*)(g_xl + (long long)sn * HC_);
            l0 = pn[lane];
            l1 = pn[lane + 32];
        }
        float v, s0 = 0.f, s1 = 0.f;
        v = cl0.x + r0.x; v = (v > 0.f) ? v : SLOPE_ * v; s0 += v * a0.x;
        v = cl0.y + r0.y; v = (v > 0.f) ? v : SLOPE_ * v; s0 += v * a0.y;
        v = cl0.z + r0.z; v = (v > 0.f) ? v : SLOPE_ * v; s0 += v * a0.z;
        v = cl0.w + r0.w; v = (v > 0.f) ? v : SLOPE_ * v; s0 += v * a0.w;
        v = cl1.x + r1.x; v = (v > 0.f) ? v : SLOPE_ * v; s1 += v * a1.x;
        v = cl1.y + r1.y; v = (v > 0.f) ? v : SLOPE_ * v; s1 += v * a1.y;
        v = cl1.z + r1.z; v = (v > 0.f) ? v : SLOPE_ * v; s1 += v * a1.z;
        v = cl1.w + r1.w; v = (v > 0.f) ? v : SLOPE_ * v; s1 += v * a1.w;
#pragma unroll
        for (int off = 4; off; off >>= 1) {
            s0 += __shfl_xor_sync(0xffffffffu, s0, off);
            s1 += __shfl_xor_sync(0xffffffffu, s1, off);
        }
        float nm0 = fmaxf(mx0, s0);
        float c0 = __expf(mx0 - nm0);
        float w0 = __expf(s0 - nm0);
        mx0 = nm0;
        den0 = den0 * c0 + w0;
        ac0.x = ac0.x * c0 + w0 * cl0.x;
        ac0.y = ac0.y * c0 + w0 * cl0.y;
        ac0.z = ac0.z * c0 + w0 * cl0.z;
        ac0.w = ac0.w * c0 + w0 * cl0.w;
        float nm1 = fmaxf(mx1, s1);
        float c1 = __expf(mx1 - nm1);
        float w1 = __expf(s1 - nm1);
        mx1 = nm1;
        den1 = den1 * c1 + w1;
        ac1.x = ac1.x * c1 + w1 * cl1.x;
        ac1.y = ac1.y * c1 + w1 * cl1.y;
        ac1.z = ac1.z * c1 + w1 * cl1.z;
        ac1.w = ac1.w * c1 + w1 * cl1.w;
    }
    float i0 = 1.f / den0, i1 = 1.f / den1;
    o0 = make_float4(ac0.x * i0, ac0.y * i0, ac0.z * i0, ac0.w * i0);
    o1 = make_float4(ac1.x * i1, ac1.y * i1, ac1.z * i1, ac1.w * i1);
}

// layer 0: h = elu(bn(out + b0)) -> tf32-rounded fp32 into g_af [N, 256]
__global__ void gat_layer0(const float* __restrict__ att,
                           const float* __restrict__ b0, const float* __restrict__ g0,
                           const float* __restrict__ be0, const float* __restrict__ m0,
                           const float* __restrict__ v0, int N) {
    int lane = threadIdx.x & 31;
    int n = (blockIdx.x * blockDim.x + threadIdx.x) >> 5;
    if (n >= N) return;
    float4 o0, o1;
    gat_core(n, lane, (const float4*)att, o0, o1);
    float out[8] = {o0.x, o0.y, o0.z, o0.w, o1.x, o1.y, o1.z, o1.w};
    float4* ph = (float4*)(g_af + (size_t)n * HC_);
#pragma unroll
    for (int half = 0; half < 2; half++) {
        int q = lane + half * 32;
        float4 bb = ((const float4*)b0)[q];
        float4 gg = ((const float4*)g0)[q];
        float4 be = ((const float4*)be0)[q];
        float4 mm = ((const float4*)m0)[q];
        float4 vv = ((const float4*)v0)[q];
        float xb[4] = {out[half*4+0] + bb.x, out[half*4+1] + bb.y,
                       out[half*4+2] + bb.z, out[half*4+3] + bb.w};
        float mu[4] = {mm.x, mm.y, mm.z, mm.w};
        float va[4] = {vv.x, vv.y, vv.z, vv.w};
        float ga[4] = {gg.x, gg.y, gg.z, gg.w};
        float ba[4] = {be.x, be.y, be.z, be.w};
        float r[4];
#pragma unroll
        for (int j = 0; j < 4; j++) {
            float xv = (xb[j] - mu[j]) * rsqrtf(va[j] + EPS_) * ga[j] + ba[j];
            float rr = (xv > 0.f) ? xv : (__expf(xv) - 1.f);
            r[j] = tf32r(rr);
        }
        ph[q] = make_float4(r[0], r[1], r[2], r[3]);
    }
}

// layer 1: s = bn(mean_h(out) + b1); y = s @ Wc + bc  -> out [N, 2]
__global__ void gat_layer1(const float* __restrict__ att,
                           const float* __restrict__ b1, const float* __restrict__ g1,
                           const float* __restrict__ be1, const float* __restrict__ m1,
                           const float* __restrict__ v1, const float* __restrict__ Wc,
                           const float* __restrict__ bc, float* __restrict__ outp, int N) {
    int lane = threadIdx.x & 31;
    int n = (blockIdx.x * blockDim.x + threadIdx.x) >> 5;
    if (n >= N) return;
    float4 o0, o1;
    gat_core(n, lane, (const float4*)att, o0, o1);
    float t0 = o0.x + o1.x, t1 = o0.y + o1.y, t2 = o0.z + o1.z, t3 = o0.w + o1.w;
#pragma unroll
    for (int off = 8; off <= 16; off <<= 1) {
        t0 += __shfl_xor_sync(0xffffffffu, t0, off);
        t1 += __shfl_xor_sync(0xffffffffu, t1, off);
        t2 += __shfl_xor_sync(0xffffffffu, t2, off);
        t3 += __shfl_xor_sync(0xffffffffu, t3, off);
    }
    int cg = lane & 7;
    float4 bb = ((const float4*)b1)[cg];
    float4 gg = ((const float4*)g1)[cg];
    float4 be = ((const float4*)be1)[cg];
    float4 mm = ((const float4*)m1)[cg];
    float4 vv = ((const float4*)v1)[cg];
    float s0 = (t0 * 0.125f + bb.x - mm.x) * rsqrtf(vv.x + EPS_) * gg.x + be.x;
    float s1 = (t1 * 0.125f + bb.y - mm.y) * rsqrtf(vv.y + EPS_) * gg.y + be.y;
    float s2 = (t2 * 0.125f + bb.z - mm.z) * rsqrtf(vv.z + EPS_) * gg.z + be.z;
    float s3 = (t3 * 0.125f + bb.w - mm.w) * rsqrtf(vv.w + EPS_) * gg.w + be.w;
    int c0 = cg * 4;
    float y0 = s0 * Wc[(c0+0)*2] + s1 * Wc[(c0+1)*2] + s2 * Wc[(c0+2)*2] + s3 * Wc[(c0+3)*2];
    float y1 = s0 * Wc[(c0+0)*2+1] + s1 * Wc[(c0+1)*2+1] + s2 * Wc[(c0+2)*2+1] + s3 * Wc[(c0+3)*2+1];
#pragma unroll
    for (int off = 4; off; off >>= 1) {
        y0 += __shfl_xor_sync(0xffffffffu, y0, off);
        y1 += __shfl_xor_sync(0xffffffffu, y1, off);
    }
    if (lane == 0) {
        outp[(long long)n * 2 + 0] = y0 + bc[0];
        outp[(long long)n * 2 + 1] = y1 + bc[1];
    }
}

// ---------------------------------------------------------------------------
extern "C" void kernel_launch(void* const* d_in, const int* in_sizes, int n_in,
                              void* d_out, int out_size) {
    const float* x    = (const float*)d_in[0];
    const void*  ei   = d_in[1];
    const float* Wl0  = (const float*)d_in[2];
    const float* Wr0  = (const float*)d_in[3];
    const float* att0 = (const float*)d_in[4];
    const float* b0   = (const float*)d_in[5];
    const float* g0   = (const float*)d_in[6];
    const float* be0  = (const float*)d_in[7];
    const float* m0   = (const float*)d_in[8];
    const float* v0   = (const float*)d_in[9];
    const float* Wl1  = (const float*)d_in[10];
    const float* Wr1  = (const float*)d_in[11];
    const float* att1 = (const float*)d_in[12];
    const float* b1   = (const float*)d_in[13];
    const float* g1   = (const float*)d_in[14];
    const float* be1  = (const float*)d_in[15];
    const float* m1   = (const float*)d_in[16];
    const float* v1   = (const float*)d_in[17];
    const float* Wc   = (const float*)d_in[18];
    const float* bc   = (const float*)d_in[19];
    float* out = (float*)d_out;

    int IN = in_sizes[2] / HC_;       // 128
    int N  = in_sizes[0] / IN;        // 50000
    int E  = in_sizes[1] / 2;         // 800000
    int Etot = E + N;
    int nb = (N + SCAN_B - 1) / SCAN_B;

    void *p_xl, *p_xr, *p_cnt, *p_af, *p_wt;
    cudaGetSymbolAddress(&p_xl,  g_xl);
    cudaGetSymbolAddress(&p_xr,  g_xr);
    cudaGetSymbolAddress(&p_cnt, g_cnt);
    cudaGetSymbolAddress(&p_af,  g_af);
    cudaGetSymbolAddress(&p_wt,  g_wt);
    float* af = (float*)p_af;
    float* wt = (float*)p_wt;
    float* xl = (float*)p_xl;
    float* xr = (float*)p_xr;
    const size_t WSZ = 256 * 256;

    // ONE side stream + two events — identical graph topology to the last
    // cleanly-passing run (round 13). Do not add streams: the 2-stream graph
    // trips a 2MB post-teardown driver-pool residue (harness rule violation).
    cudaStream_t s1;
    cudaStreamCreateWithFlags(&s1, cudaStreamNonBlocking);
    cudaEvent_t eFork, eJoin;
    cudaEventCreateWithFlags(&eFork, cudaEventDisableTiming);
    cudaEventCreateWithFlags(&eJoin, cudaEventDisableTiming);
    cudaEventRecord(eFork, 0);
    cudaStreamWaitEvent(s1, eFork, 0);

    // ---- side stream: CSR build + layer-1 weight transposes ----
    k_detect<<<1, 1, 0, s1>>>((const int*)ei, E);
    cudaMemsetAsync(p_cnt, 0, (size_t)N * sizeof(int), s1);
    k_convert<<<(2 * E + 255) / 256, 256, 0, s1>>>(ei, E);
    k_scan_a<<<nb, SCAN_B, 0, s1>>>(N);
    k_scan_b<<<1, SCAN_B, 0, s1>>>(nb);
    k_scan_c<<<nb, SCAN_B, 0, s1>>>(N);
    k_scatter<<<(Etot + 255) / 256, 256, 0, s1>>>(E, N);
    k_trans_w<<<(HC_ * HC_ + 255) / 256, 256, 0, s1>>>(Wl1, wt + 2 * WSZ, HC_, HC_);
    k_trans_w<<<(HC_ * HC_ + 255) / 256, 256, 0, s1>>>(Wr1, wt + 3 * WSZ, HC_, HC_);
    cudaEventRecord(eJoin, s1);

    // ---- main stream: layer-0 weight transposes (A rounded in-kernel) ----
    k_trans_w<<<(IN * HC_ + 255) / 256, 256>>>(Wl0, wt, IN, HC_);
    k_trans_w<<<(IN * HC_ + 255) / 256, 256>>>(Wr0, wt + WSZ, IN, HC_);

    dim3 g0grid(HC_ / BN, (N + BM - 1) / BM, 2);
    int nodeBlocks = (N * 32 + 255) / 256;

    // ---------------- layer 0 (K = IN = 128, A = raw x, rounded in-kernel) --
    tf32_gemm<<<g0grid, 256>>>(x, wt, wt + WSZ, xl, xr, N, IN, HC_);
    cudaStreamWaitEvent(0, eJoin, 0);
    gat_layer0<<<nodeBlocks, 256>>>(att0, b0, g0, be0, m0, v0, N);

    // ---------------- layer 1 (K = HC = 256) ----------------
    tf32_gemm<<<g0grid, 256>>>(af, wt + 2 * WSZ, wt + 3 * WSZ,
                               xl, xr, N, HC_, HC_);
    gat_layer1<<<nodeBlocks, 256>>>(att1, b1, g1, be1, m1, v1, Wc, bc, out, N);
}